// round 1
// baseline (speedup 1.0000x reference)
#include <cuda_runtime.h>

// ---------------- problem constants ----------------
#define BN     4
#define CCH    288
#define HWSZ   4096            // 64*64
#define SN     (CCH*HWSZ)      // 1179648 per-sample elements
#define DD     1152
#define SIXC   1728
#define STOK   1024            // spatial tokens (32x32)
#define SSEQ   1026            // + global + time
#define NHEADS 36
#define HFF    4608
#define HF2    9216
#define LNB    144             // ln partial blocks per sample

// ---------------- scratch (static device memory; no allocations) ----------------
__device__ float g_ss   [BN*SIXC*HWSZ];     // 6C scale/shift maps
__device__ float g_tok  [BN*SSEQ*DD];
__device__ float g_qkv  [BN*SSEQ*3*DD];
__device__ float g_attn [BN*STOK*DD];       // normalized attn out, tokens 2..1025
__device__ float g_aproj[BN*STOK*DD];
__device__ float g_x1   [BN*SN];
__device__ float g_t2T  [BN*DD*STOK];       // transposed tokens for NN gemm
__device__ float g_hexp [BN*HF2*STOK];
__device__ float g_hglu [BN*HFF*STOK];
__device__ float g_mT   [BN*DD*STOK];
__device__ float g_psum [BN*LNB];
__device__ float g_psumsq[BN*LNB];
__device__ float g_stats[BN*2];             // mu, rsig per sample

__device__ __forceinline__ float siluf(float v) { return v / (1.0f + __expf(-v)); }

// ---------------- generic tiled SGEMM ----------------
// C[M,N] = A[M,K] * op(B) ; TRANSB=false: B[K,N], true: B[N,K] (C = A*B^T)
// N % 128 == 0, K % 8 == 0 (true for every call here); M guarded.
// blockIdx.z batches B and C (A shared).
// BIASMODE: 0 none, 1 bias[m], 2 bias[n].  B_SILU: silu() on B elements.  ACT_SILU: silu on C.
template<bool TRANSB, bool B_SILU, int BIASMODE, bool ACT_SILU>
__global__ __launch_bounds__(256)
void gemm_k(const float* __restrict__ A, const float* __restrict__ B,
            float* __restrict__ C, const float* __restrict__ bias,
            int M, int N, int K, long long strideB, long long strideC)
{
    __shared__ float As[8][128];
    __shared__ float Bs[8][128];
    const float* Bz = B + (long long)blockIdx.z * strideB;
    float*       Cz = C + (long long)blockIdx.z * strideC;
    const int tid = threadIdx.x;
    const int tx = tid & 15, ty = tid >> 4;
    const int row0 = blockIdx.y * 128;
    const int col0 = blockIdx.x * 128;

    float acc[8][8];
#pragma unroll
    for (int i = 0; i < 8; i++)
#pragma unroll
        for (int j = 0; j < 8; j++) acc[i][j] = 0.f;

    const int am = tid >> 1;
    const int ak = (tid & 1) * 4;

    for (int k0 = 0; k0 < K; k0 += 8) {
        // A tile: 128 rows x 8 k
        {
            int arow = row0 + am;
            float4 av = make_float4(0.f, 0.f, 0.f, 0.f);
            if (arow < M) av = *(const float4*)(A + (long long)arow * K + k0 + ak);
            As[ak + 0][am] = av.x; As[ak + 1][am] = av.y;
            As[ak + 2][am] = av.z; As[ak + 3][am] = av.w;
        }
        // B tile: 8 k x 128 n
        if (!TRANSB) {
            int bk = tid >> 5;
            int bn = (tid & 31) * 4;
            float4 bv = *(const float4*)(Bz + (long long)(k0 + bk) * N + col0 + bn);
            if (B_SILU) { bv.x = siluf(bv.x); bv.y = siluf(bv.y); bv.z = siluf(bv.z); bv.w = siluf(bv.w); }
            *(float4*)&Bs[bk][bn] = bv;
        } else {
            int bn = tid >> 1;
            int bk = (tid & 1) * 4;
            float4 bv = *(const float4*)(Bz + (long long)(col0 + bn) * K + k0 + bk);
            Bs[bk + 0][bn] = bv.x; Bs[bk + 1][bn] = bv.y;
            Bs[bk + 2][bn] = bv.z; Bs[bk + 3][bn] = bv.w;
        }
        __syncthreads();

#pragma unroll
        for (int kk = 0; kk < 8; kk++) {
            float a[8], b[8];
            *(float4*)&a[0] = *(const float4*)&As[kk][ty * 8];
            *(float4*)&a[4] = *(const float4*)&As[kk][ty * 8 + 4];
            *(float4*)&b[0] = *(const float4*)&Bs[kk][tx * 8];
            *(float4*)&b[4] = *(const float4*)&Bs[kk][tx * 8 + 4];
#pragma unroll
            for (int i = 0; i < 8; i++)
#pragma unroll
                for (int j = 0; j < 8; j++) acc[i][j] += a[i] * b[j];
        }
        __syncthreads();
    }

#pragma unroll
    for (int i = 0; i < 8; i++) {
        int r = row0 + ty * 8 + i;
        if (r >= M) break;
        float bm = (BIASMODE == 1) ? bias[r] : 0.f;
#pragma unroll
        for (int j = 0; j < 8; j += 4) {
            int cidx = col0 + tx * 8 + j;
            float4 v = make_float4(acc[i][j], acc[i][j + 1], acc[i][j + 2], acc[i][j + 3]);
            if (BIASMODE == 1) { v.x += bm; v.y += bm; v.z += bm; v.w += bm; }
            if (BIASMODE == 2) {
                v.x += bias[cidx]; v.y += bias[cidx + 1];
                v.z += bias[cidx + 2]; v.w += bias[cidx + 3];
            }
            if (ACT_SILU) { v.x = siluf(v.x); v.y = siluf(v.y); v.z = siluf(v.z); v.w = siluf(v.w); }
            *(float4*)(Cz + (long long)r * N + cidx) = v;
        }
    }
}

// ---------------- LayerNorm (whole-sample) reduction ----------------
__global__ void ln_partial_k(const float* __restrict__ x,
                             float* __restrict__ psum, float* __restrict__ psumsq)
{
    int b = blockIdx.y;
    const float* xb = x + (long long)b * SN;
    const int chunk = SN / LNB;  // 8192
    int base = blockIdx.x * chunk;
    float s = 0.f, sq = 0.f;
    for (int i = base + threadIdx.x; i < base + chunk; i += 256) {
        float v = xb[i]; s += v; sq += v * v;
    }
    __shared__ float sh1[256], sh2[256];
    sh1[threadIdx.x] = s; sh2[threadIdx.x] = sq;
    __syncthreads();
    for (int o = 128; o > 0; o >>= 1) {
        if (threadIdx.x < o) {
            sh1[threadIdx.x] += sh1[threadIdx.x + o];
            sh2[threadIdx.x] += sh2[threadIdx.x + o];
        }
        __syncthreads();
    }
    if (threadIdx.x == 0) {
        psum[b * LNB + blockIdx.x] = sh1[0];
        psumsq[b * LNB + blockIdx.x] = sh2[0];
    }
}

__global__ void ln_final_k(const float* __restrict__ psum, const float* __restrict__ psumsq,
                           float* __restrict__ stats)
{
    int b = blockIdx.x;
    float s = 0.f, sq = 0.f;
    for (int i = threadIdx.x; i < LNB; i += 256) { s += psum[b * LNB + i]; sq += psumsq[b * LNB + i]; }
    __shared__ float sh1[256], sh2[256];
    sh1[threadIdx.x] = s; sh2[threadIdx.x] = sq;
    __syncthreads();
    for (int o = 128; o > 0; o >>= 1) {
        if (threadIdx.x < o) {
            sh1[threadIdx.x] += sh1[threadIdx.x + o];
            sh2[threadIdx.x] += sh2[threadIdx.x + o];
        }
        __syncthreads();
    }
    if (threadIdx.x == 0) {
        float mu = sh1[0] / (float)SN;
        float var = sh2[0] / (float)SN - mu * mu;
        stats[b * 2 + 0] = mu;
        stats[b * 2 + 1] = rsqrtf(var + 1e-6f);
    }
}

// ---------------- token init (global/time) ----------------
__global__ void tokinit_k(const float* __restrict__ gt, const float* __restrict__ tt,
                          float* __restrict__ tok)
{
    int gid = blockIdx.x * blockDim.x + threadIdx.x;
    if (gid >= BN * DD) return;
    int b = gid / DD, j = gid % DD;
    tok[((long long)b * SSEQ + 0) * DD + j] = gt[b * DD + j];
    tok[((long long)b * SSEQ + 1) * DD + j] = tt[b * DD + j];
}

// ---------------- MSA modulate + segment: tok[b][2+t][j] ----------------
__global__ void msa_seg_k(const float* __restrict__ x, const float* __restrict__ ss,
                          const float* __restrict__ stats, float* __restrict__ tok)
{
    long long gid = (long long)blockIdx.x * blockDim.x + threadIdx.x;
    if (gid >= (long long)BN * STOK * DD) return;
    int j = (int)(gid % DD);
    int t = (int)((gid / DD) % STOK);
    int b = (int)(gid / ((long long)STOK * DD));
    int c = j >> 2, p1 = (j >> 1) & 1, p2 = j & 1;
    int n1 = t >> 5, n2 = t & 31;
    int hw = ((2 * n1 + p1) << 6) + 2 * n2 + p2;
    float mu = stats[b * 2], rsig = stats[b * 2 + 1];
    float xv = x[((long long)b * CCH + c) * HWSZ + hw];
    float sc = ss[((long long)b * SIXC + 288 + c) * HWSZ + hw];
    float sh = ss[((long long)b * SIXC + c) * HWSZ + hw];
    tok[((long long)b * SSEQ + 2 + t) * DD + j] = (xv - mu) * rsig * (1.f + sc) + sh;
}

// ---------------- linear attention (one block per (b, head)) ----------------
__global__ void attn_k(const float* __restrict__ qkv, float* __restrict__ attn)
{
    int h = blockIdx.x, b = blockIdx.y;
    int tid = threadIdx.x;
    __shared__ float vk[33 * 32];
    __shared__ float ks[8][32];
    __shared__ float vs[8][33];
    float acc[5] = {0.f, 0.f, 0.f, 0.f, 0.f};
    const float* qkvb = qkv + (long long)b * SSEQ * (3 * DD);

    for (int s0 = 0; s0 < SSEQ; s0 += 8) {
        {   // load 8 tokens of k (relu) — 256 loads exactly
            int si = tid >> 5, d = tid & 31;
            int s = s0 + si;
            ks[si][d] = (s < SSEQ) ? fmaxf(qkvb[(long long)s * (3 * DD) + DD + h * 32 + d], 0.f) : 0.f;
        }
        for (int idx = tid; idx < 8 * 33; idx += 256) {   // v with ones padding
            int si = idx / 33, e = idx % 33;
            int s = s0 + si;
            float vv = 0.f;
            if (s < SSEQ) vv = (e < 32) ? qkvb[(long long)s * (3 * DD) + 2 * DD + h * 32 + e] : 1.f;
            vs[si][e] = vv;
        }
        __syncthreads();
#pragma unroll
        for (int si = 0; si < 8; si++) {
#pragma unroll
            for (int r = 0; r < 5; r++) {
                int f = tid + (r << 8);
                if (f < 1056) acc[r] += vs[si][f >> 5] * ks[si][f & 31];
            }
        }
        __syncthreads();
    }
#pragma unroll
    for (int r = 0; r < 5; r++) {
        int f = tid + (r << 8);
        if (f < 1056) vk[f] = acc[r];
    }
    __syncthreads();

    for (int s = tid; s < SSEQ; s += 256) {
        float q[32];
        const float* qp = qkvb + (long long)s * (3 * DD) + h * 32;
#pragma unroll
        for (int d4 = 0; d4 < 32; d4 += 4) {
            float4 qv = *(const float4*)(qp + d4);
            q[d4 + 0] = fmaxf(qv.x, 0.f); q[d4 + 1] = fmaxf(qv.y, 0.f);
            q[d4 + 2] = fmaxf(qv.z, 0.f); q[d4 + 3] = fmaxf(qv.w, 0.f);
        }
        float den = 0.f;
#pragma unroll
        for (int d = 0; d < 32; d++) den += vk[32 * 32 + d] * q[d];
        float inv = 1.0f / (den + 1e-8f);
        if (s >= 2) {
            float* op = attn + ((long long)(b * STOK + s - 2)) * DD + h * 32;
            for (int e = 0; e < 32; e++) {
                float num = 0.f;
#pragma unroll
                for (int d = 0; d < 32; d++) num += vk[e * 32 + d] * q[d];
                op[e] = num * inv;
            }
        }
    }
}

// ---------------- comb(a)*g_msa + residual -> x1 ----------------
__global__ void comb1_k(const float* __restrict__ x, const float* __restrict__ a,
                        const float* __restrict__ ss, float* __restrict__ x1)
{
    long long gid = (long long)blockIdx.x * blockDim.x + threadIdx.x;
    if (gid >= (long long)BN * SN) return;
    int hw = (int)(gid % HWSZ);
    int c = (int)((gid / HWSZ) % CCH);
    int b = (int)(gid / SN);
    int hh = hw >> 6, ww = hw & 63;
    int t = ((hh >> 1) << 5) + (ww >> 1);
    int j = (c << 2) + ((hh & 1) << 1) + (ww & 1);
    float g = ss[((long long)b * SIXC + 576 + c) * HWSZ + hw];
    x1[gid] = x[gid] + a[((long long)(b * STOK + t)) * DD + j] * g;
}

// ---------------- MLP modulate + segment (transposed): t2T[b][j][n] ----------------
__global__ void mlp_segT_k(const float* __restrict__ x1, const float* __restrict__ ss,
                           const float* __restrict__ stats, float* __restrict__ t2T)
{
    long long gid = (long long)blockIdx.x * blockDim.x + threadIdx.x;
    if (gid >= (long long)BN * DD * STOK) return;
    int n = (int)(gid % STOK);
    int j = (int)((gid / STOK) % DD);
    int b = (int)(gid / ((long long)DD * STOK));
    int c = j >> 2, p1 = (j >> 1) & 1, p2 = j & 1;
    int n1 = n >> 5, n2 = n & 31;
    int hw = ((2 * n1 + p1) << 6) + 2 * n2 + p2;
    float mu = stats[b * 2], rsig = stats[b * 2 + 1];
    float xv = x1[((long long)b * CCH + c) * HWSZ + hw];
    float sc = ss[((long long)b * SIXC + 1152 + c) * HWSZ + hw];
    float sh = ss[((long long)b * SIXC + 864 + c) * HWSZ + hw];
    t2T[gid] = (xv - mu) * rsig * (1.f + sc) + sh;
}

// ---------------- depthwise 3x3 + GLU gate ----------------
__global__ void dwglu_k(const float* __restrict__ hexp, const float* __restrict__ dw_w,
                        const float* __restrict__ dw_b, float* __restrict__ hglu)
{
    long long gid = (long long)blockIdx.x * blockDim.x + threadIdx.x;
    if (gid >= (long long)BN * HFF * STOK) return;
    int n = (int)(gid % STOK);
    int ch = (int)((gid / STOK) % HFF);
    int b = (int)(gid / ((long long)HFF * STOK));
    int y = n >> 5, xx = n & 31;
    const float* pa = hexp + ((long long)b * HF2 + ch) * STOK;
    const float* pg = hexp + ((long long)b * HF2 + ch + HFF) * STOK;
    const float* wa = dw_w + ch * 9;
    const float* wg = dw_w + (ch + HFF) * 9;
    float va = dw_b[ch], vg = dw_b[ch + HFF];
#pragma unroll
    for (int ky = -1; ky <= 1; ky++) {
        int yy = y + ky;
        if ((unsigned)yy >= 32u) continue;
#pragma unroll
        for (int kx = -1; kx <= 1; kx++) {
            int xc = xx + kx;
            if ((unsigned)xc >= 32u) continue;
            int nn = (yy << 5) + xc;
            int wi = (ky + 1) * 3 + (kx + 1);
            va += wa[wi] * pa[nn];
            vg += wg[wi] * pg[nn];
        }
    }
    hglu[gid] = va * siluf(vg);
}

// ---------------- comb(m)*g_mlp + residual -> out ----------------
__global__ void comb2_k(const float* __restrict__ x1, const float* __restrict__ mT,
                        const float* __restrict__ ss, float* __restrict__ out)
{
    long long gid = (long long)blockIdx.x * blockDim.x + threadIdx.x;
    if (gid >= (long long)BN * SN) return;
    int hw = (int)(gid % HWSZ);
    int c = (int)((gid / HWSZ) % CCH);
    int b = (int)(gid / SN);
    int hh = hw >> 6, ww = hw & 63;
    int t = ((hh >> 1) << 5) + (ww >> 1);
    int j = (c << 2) + ((hh & 1) << 1) + (ww & 1);
    float g = ss[((long long)b * SIXC + 1440 + c) * HWSZ + hw];
    out[gid] = x1[gid] + mT[((long long)b * DD + j) * STOK + t] * g;
}

// ---------------- launch ----------------
extern "C" void kernel_launch(void* const* d_in, const int* in_sizes, int n_in,
                              void* d_out, int out_size)
{
    const float* x      = (const float*)d_in[0];
    const float* cond   = (const float*)d_in[1];
    const float* gtok   = (const float*)d_in[2];
    const float* ttok   = (const float*)d_in[3];
    const float* ss_w   = (const float*)d_in[4];
    const float* ss_b   = (const float*)d_in[5];
    const float* qkv_w  = (const float*)d_in[6];
    const float* proj_w = (const float*)d_in[7];
    const float* proj_b = (const float*)d_in[8];
    const float* inv_w  = (const float*)d_in[9];
    const float* inv_b  = (const float*)d_in[10];
    const float* dw_w   = (const float*)d_in[11];
    const float* dw_b   = (const float*)d_in[12];
    const float* pw_w   = (const float*)d_in[13];
    float* out = (float*)d_out;

    float *p_ss, *p_tok, *p_qkv, *p_attn, *p_aproj, *p_x1, *p_t2T, *p_hexp, *p_hglu, *p_mT,
          *p_psum, *p_psumsq, *p_stats;
    cudaGetSymbolAddress((void**)&p_ss, g_ss);
    cudaGetSymbolAddress((void**)&p_tok, g_tok);
    cudaGetSymbolAddress((void**)&p_qkv, g_qkv);
    cudaGetSymbolAddress((void**)&p_attn, g_attn);
    cudaGetSymbolAddress((void**)&p_aproj, g_aproj);
    cudaGetSymbolAddress((void**)&p_x1, g_x1);
    cudaGetSymbolAddress((void**)&p_t2T, g_t2T);
    cudaGetSymbolAddress((void**)&p_hexp, g_hexp);
    cudaGetSymbolAddress((void**)&p_hglu, g_hglu);
    cudaGetSymbolAddress((void**)&p_mT, g_mT);
    cudaGetSymbolAddress((void**)&p_psum, g_psum);
    cudaGetSymbolAddress((void**)&p_psumsq, g_psumsq);
    cudaGetSymbolAddress((void**)&p_stats, g_stats);

    // 1) scale_shift: per-batch  ss[b] = ss_w @ silu(cond[b]) + ss_b
    gemm_k<false, true, 1, false><<<dim3(HWSZ / 128, (SIXC + 127) / 128, BN), 256>>>(
        ss_w, cond, p_ss, ss_b, SIXC, HWSZ, SIXC,
        (long long)SIXC * HWSZ, (long long)SIXC * HWSZ);

    // 2) LayerNorm(x)
    ln_partial_k<<<dim3(LNB, BN), 256>>>(x, p_psum, p_psumsq);
    ln_final_k<<<BN, 256>>>(p_psum, p_psumsq, p_stats);

    // 3) tokens
    tokinit_k<<<(BN * DD + 255) / 256, 256>>>(gtok, ttok, p_tok);
    msa_seg_k<<<(int)(((long long)BN * STOK * DD + 255) / 256), 256>>>(x, p_ss, p_stats, p_tok);

    // 4) qkv = tok @ qkv_w^T
    gemm_k<true, false, 0, false><<<dim3((3 * DD) / 128, (BN * SSEQ + 127) / 128, 1), 256>>>(
        p_tok, qkv_w, p_qkv, nullptr, BN * SSEQ, 3 * DD, DD, 0, 0);

    // 5) linear attention
    attn_k<<<dim3(NHEADS, BN), 256>>>(p_qkv, p_attn);

    // 6) proj (tokens 2.. only) = attn @ proj_w^T + proj_b
    gemm_k<true, false, 2, false><<<dim3(DD / 128, (BN * STOK) / 128, 1), 256>>>(
        p_attn, proj_w, p_aproj, proj_b, BN * STOK, DD, DD, 0, 0);

    // 7) x1 = x + comb(a)*g_msa
    comb1_k<<<(int)(((long long)BN * SN + 255) / 256), 256>>>(x, p_aproj, p_ss, p_x1);

    // 8) LayerNorm(x1)
    ln_partial_k<<<dim3(LNB, BN), 256>>>(p_x1, p_psum, p_psumsq);
    ln_final_k<<<BN, 256>>>(p_psum, p_psumsq, p_stats);

    // 9) MLP modulate+segment (transposed layout)
    mlp_segT_k<<<(int)(((long long)BN * DD * STOK + 255) / 256), 256>>>(p_x1, p_ss, p_stats, p_t2T);

    // 10) expand: hexp[b] = silu(inv_w @ t2T[b] + inv_b)
    gemm_k<false, false, 1, true><<<dim3(STOK / 128, HF2 / 128, BN), 256>>>(
        inv_w, p_t2T, p_hexp, inv_b, HF2, STOK, DD,
        (long long)DD * STOK, (long long)HF2 * STOK);

    // 11) depthwise 3x3 + GLU
    dwglu_k<<<(int)(((long long)BN * HFF * STOK + 255) / 256), 256>>>(p_hexp, dw_w, dw_b, p_hglu);

    // 12) project: mT[b] = pw_w @ hglu[b]
    gemm_k<false, false, 0, false><<<dim3(STOK / 128, DD / 128, BN), 256>>>(
        pw_w, p_hglu, p_mT, nullptr, DD, STOK, HFF,
        (long long)HFF * STOK, (long long)DD * STOK);

    // 13) out = x1 + comb(m)*g_mlp
    comb2_k<<<(int)(((long long)BN * SN + 255) / 256), 256>>>(p_x1, p_mT, p_ss, out);
}

// round 2
// speedup vs baseline: 2.2162x; 2.2162x over previous
#include <cuda_runtime.h>

// ---------------- problem constants ----------------
#define BN     4
#define CCH    288
#define HWSZ   4096            // 64*64
#define SN     (CCH*HWSZ)      // 1179648 per-sample elements
#define DD     1152
#define SIXC   1728
#define STOK   1024            // spatial tokens (32x32)
#define SSEQ   1026            // + global + time
#define NHEADS 36
#define HFF    4608
#define HF2    9216
#define LNB    144             // ln partial blocks per sample

// ---------------- scratch (static device memory; no allocations) ----------------
__device__ float g_ss   [BN*SIXC*HWSZ];     // 6C scale/shift maps
__device__ float g_tok  [BN*SSEQ*DD];
__device__ float g_qkv  [BN*SSEQ*3*DD];
__device__ float g_attn [BN*STOK*DD];       // normalized attn out, tokens 2..1025
__device__ float g_aproj[BN*STOK*DD];
__device__ float g_x1   [BN*SN];
__device__ float g_t2T  [BN*DD*STOK];       // transposed tokens for NN gemm
__device__ float g_hexp [BN*HF2*STOK];
__device__ float g_hglu [BN*HFF*STOK];
__device__ float g_mT   [BN*DD*STOK];
__device__ float g_psum [BN*LNB];
__device__ float g_psumsq[BN*LNB];
__device__ float g_stats[BN*2];             // mu, rsig per sample

__device__ __forceinline__ float siluf(float v) { return v / (1.0f + __expf(-v)); }

__device__ __forceinline__ float tf32r(float x) {
    unsigned u;
    asm("cvt.rna.tf32.f32 %0, %1;" : "=r"(u) : "f"(x));
    return __uint_as_float(u);
}

__device__ __forceinline__ void mma_tf32(float c[4], const float a[4], const float b[2]) {
    asm volatile(
        "mma.sync.aligned.m16n8k8.row.col.f32.tf32.tf32.f32 "
        "{%0,%1,%2,%3}, {%4,%5,%6,%7}, {%8,%9}, {%0,%1,%2,%3};"
        : "+f"(c[0]), "+f"(c[1]), "+f"(c[2]), "+f"(c[3])
        : "r"(__float_as_uint(a[0])), "r"(__float_as_uint(a[1])),
          "r"(__float_as_uint(a[2])), "r"(__float_as_uint(a[3])),
          "r"(__float_as_uint(b[0])), "r"(__float_as_uint(b[1])));
}

// ---------------- tf32 tensor-core GEMM ----------------
// C[M,N] = A[M,K] * op(B) ; TRANSB=false: B[K,N], true: B[N,K] (C = A*B^T)
// Requirements: N % 128 == 0, K % 16 == 0 (all call sites satisfy); M guarded.
// blockIdx.z batches B and C (A shared across z).
// BIASMODE: 0 none, 1 bias[m], 2 bias[n].  B_SILU: silu(B) before use.  ACT_SILU: silu on C.
template<bool TRANSB, bool B_SILU, int BIASMODE, bool ACT_SILU>
__global__ __launch_bounds__(256)
void gemm_tc(const float* __restrict__ A, const float* __restrict__ B,
             float* __restrict__ C, const float* __restrict__ bias,
             int M, int N, int K, long long strideB, long long strideC)
{
    // A: [m][k] layout, 128 x 16, pad row to 20 floats  -> frag loads conflict-free
    __shared__ float As[128][20];
    // B: TRANSB ? [n][k] 128x20 : [k][n] 16x136          -> frag loads conflict-free
    __shared__ float Bs[TRANSB ? 128 : 16][TRANSB ? 20 : 136];

    const float* Bz = B + (long long)blockIdx.z * strideB;
    float*       Cz = C + (long long)blockIdx.z * strideC;

    const int tid  = threadIdx.x;
    const int lane = tid & 31;
    const int warp = tid >> 5;
    const int wm   = (warp & 3) * 32;     // warp M offset within block tile
    const int wn   = (warp >> 2) * 64;    // warp N offset
    const int gid  = lane >> 2;           // 0..7
    const int tig  = lane & 3;            // 0..3
    const int row0 = blockIdx.y * 128;
    const int col0 = blockIdx.x * 128;

    float acc[2][8][4];
#pragma unroll
    for (int i = 0; i < 2; i++)
#pragma unroll
        for (int j = 0; j < 8; j++)
#pragma unroll
            for (int r = 0; r < 4; r++) acc[i][j][r] = 0.f;

    for (int k0 = 0; k0 < K; k0 += 16) {
        // ---- stage A tile (128 x 16): 512 float4s, 2 per thread, vector stores
#pragma unroll
        for (int i = 0; i < 2; i++) {
            int f   = tid + i * 256;
            int row = f >> 2;
            int kq  = (f & 3) * 4;
            float4 v = make_float4(0.f, 0.f, 0.f, 0.f);
            if (row0 + row < M)
                v = *(const float4*)(A + (long long)(row0 + row) * K + k0 + kq);
            v.x = tf32r(v.x); v.y = tf32r(v.y); v.z = tf32r(v.z); v.w = tf32r(v.w);
            *(float4*)&As[row][kq] = v;
        }
        // ---- stage B tile
        if (!TRANSB) {
#pragma unroll
            for (int i = 0; i < 2; i++) {
                int f  = tid + i * 256;
                int k  = f >> 5;
                int nq = (f & 31) * 4;
                float4 v = *(const float4*)(Bz + (long long)(k0 + k) * N + col0 + nq);
                if (B_SILU) { v.x = siluf(v.x); v.y = siluf(v.y); v.z = siluf(v.z); v.w = siluf(v.w); }
                v.x = tf32r(v.x); v.y = tf32r(v.y); v.z = tf32r(v.z); v.w = tf32r(v.w);
                *(float4*)&Bs[k][nq] = v;
            }
        } else {
#pragma unroll
            for (int i = 0; i < 2; i++) {
                int f  = tid + i * 256;
                int n  = f >> 2;
                int kq = (f & 3) * 4;
                float4 v = *(const float4*)(Bz + (long long)(col0 + n) * K + k0 + kq);
                if (B_SILU) { v.x = siluf(v.x); v.y = siluf(v.y); v.z = siluf(v.z); v.w = siluf(v.w); }
                v.x = tf32r(v.x); v.y = tf32r(v.y); v.z = tf32r(v.z); v.w = tf32r(v.w);
                *(float4*)&Bs[n][kq] = v;
            }
        }
        __syncthreads();

        // ---- compute: two k8 sub-steps
#pragma unroll
        for (int kk = 0; kk < 16; kk += 8) {
            float a[2][4];
#pragma unroll
            for (int i = 0; i < 2; i++) {
                int mb = wm + i * 16;
                a[i][0] = As[mb + gid    ][kk + tig    ];
                a[i][1] = As[mb + gid + 8][kk + tig    ];
                a[i][2] = As[mb + gid    ][kk + tig + 4];
                a[i][3] = As[mb + gid + 8][kk + tig + 4];
            }
            float b[8][2];
#pragma unroll
            for (int j = 0; j < 8; j++) {
                int nb = wn + j * 8;
                if (TRANSB) {
                    b[j][0] = Bs[nb + gid][kk + tig    ];
                    b[j][1] = Bs[nb + gid][kk + tig + 4];
                } else {
                    b[j][0] = Bs[kk + tig    ][nb + gid];
                    b[j][1] = Bs[kk + tig + 4][nb + gid];
                }
            }
#pragma unroll
            for (int i = 0; i < 2; i++)
#pragma unroll
                for (int j = 0; j < 8; j++)
                    mma_tf32(acc[i][j], a[i], b[j]);
        }
        __syncthreads();
    }

    // ---- epilogue: c0,c1 at (row=gid, col=2*tig,+1); c2,c3 at row+8
#pragma unroll
    for (int i = 0; i < 2; i++) {
#pragma unroll
        for (int rr = 0; rr < 2; rr++) {
            int r = row0 + wm + i * 16 + gid + rr * 8;
            if (r >= M) continue;
            float bm = (BIASMODE == 1) ? bias[r] : 0.f;
#pragma unroll
            for (int j = 0; j < 8; j++) {
                int cc = col0 + wn + j * 8 + 2 * tig;
                float x0 = acc[i][j][2 * rr + 0];
                float x1 = acc[i][j][2 * rr + 1];
                if (BIASMODE == 1) { x0 += bm; x1 += bm; }
                if (BIASMODE == 2) { x0 += bias[cc]; x1 += bias[cc + 1]; }
                if (ACT_SILU) { x0 = siluf(x0); x1 = siluf(x1); }
                *(float2*)(Cz + (long long)r * N + cc) = make_float2(x0, x1);
            }
        }
    }
}

// ---------------- LayerNorm (whole-sample) reduction ----------------
__global__ void ln_partial_k(const float* __restrict__ x,
                             float* __restrict__ psum, float* __restrict__ psumsq)
{
    int b = blockIdx.y;
    const float* xb = x + (long long)b * SN;
    const int chunk = SN / LNB;  // 8192
    int base = blockIdx.x * chunk;
    float s = 0.f, sq = 0.f;
    for (int i = base + threadIdx.x; i < base + chunk; i += 256) {
        float v = xb[i]; s += v; sq += v * v;
    }
    __shared__ float sh1[256], sh2[256];
    sh1[threadIdx.x] = s; sh2[threadIdx.x] = sq;
    __syncthreads();
    for (int o = 128; o > 0; o >>= 1) {
        if (threadIdx.x < o) {
            sh1[threadIdx.x] += sh1[threadIdx.x + o];
            sh2[threadIdx.x] += sh2[threadIdx.x + o];
        }
        __syncthreads();
    }
    if (threadIdx.x == 0) {
        psum[b * LNB + blockIdx.x] = sh1[0];
        psumsq[b * LNB + blockIdx.x] = sh2[0];
    }
}

__global__ void ln_final_k(const float* __restrict__ psum, const float* __restrict__ psumsq,
                           float* __restrict__ stats)
{
    int b = blockIdx.x;
    float s = 0.f, sq = 0.f;
    for (int i = threadIdx.x; i < LNB; i += 256) { s += psum[b * LNB + i]; sq += psumsq[b * LNB + i]; }
    __shared__ float sh1[256], sh2[256];
    sh1[threadIdx.x] = s; sh2[threadIdx.x] = sq;
    __syncthreads();
    for (int o = 128; o > 0; o >>= 1) {
        if (threadIdx.x < o) {
            sh1[threadIdx.x] += sh1[threadIdx.x + o];
            sh2[threadIdx.x] += sh2[threadIdx.x + o];
        }
        __syncthreads();
    }
    if (threadIdx.x == 0) {
        float mu = sh1[0] / (float)SN;
        float var = sh2[0] / (float)SN - mu * mu;
        stats[b * 2 + 0] = mu;
        stats[b * 2 + 1] = rsqrtf(var + 1e-6f);
    }
}

// ---------------- token init (global/time) ----------------
__global__ void tokinit_k(const float* __restrict__ gt, const float* __restrict__ tt,
                          float* __restrict__ tok)
{
    int gid = blockIdx.x * blockDim.x + threadIdx.x;
    if (gid >= BN * DD) return;
    int b = gid / DD, j = gid % DD;
    tok[((long long)b * SSEQ + 0) * DD + j] = gt[b * DD + j];
    tok[((long long)b * SSEQ + 1) * DD + j] = tt[b * DD + j];
}

// ---------------- MSA modulate + segment: tok[b][2+t][j] ----------------
__global__ void msa_seg_k(const float* __restrict__ x, const float* __restrict__ ss,
                          const float* __restrict__ stats, float* __restrict__ tok)
{
    long long gid = (long long)blockIdx.x * blockDim.x + threadIdx.x;
    if (gid >= (long long)BN * STOK * DD) return;
    int j = (int)(gid % DD);
    int t = (int)((gid / DD) % STOK);
    int b = (int)(gid / ((long long)STOK * DD));
    int c = j >> 2, p1 = (j >> 1) & 1, p2 = j & 1;
    int n1 = t >> 5, n2 = t & 31;
    int hw = ((2 * n1 + p1) << 6) + 2 * n2 + p2;
    float mu = stats[b * 2], rsig = stats[b * 2 + 1];
    float xv = x[((long long)b * CCH + c) * HWSZ + hw];
    float sc = ss[((long long)b * SIXC + 288 + c) * HWSZ + hw];
    float sh = ss[((long long)b * SIXC + c) * HWSZ + hw];
    tok[((long long)b * SSEQ + 2 + t) * DD + j] = (xv - mu) * rsig * (1.f + sc) + sh;
}

// ---------------- linear attention (one block per (b, head)) ----------------
__global__ void attn_k(const float* __restrict__ qkv, float* __restrict__ attn)
{
    int h = blockIdx.x, b = blockIdx.y;
    int tid = threadIdx.x;
    __shared__ float vk[33 * 32];
    __shared__ float ks[8][32];
    __shared__ float vs[8][33];
    float acc[5] = {0.f, 0.f, 0.f, 0.f, 0.f};
    const float* qkvb = qkv + (long long)b * SSEQ * (3 * DD);

    for (int s0 = 0; s0 < SSEQ; s0 += 8) {
        {   // load 8 tokens of k (relu)
            int si = tid >> 5, d = tid & 31;
            int s = s0 + si;
            ks[si][d] = (s < SSEQ) ? fmaxf(qkvb[(long long)s * (3 * DD) + DD + h * 32 + d], 0.f) : 0.f;
        }
        for (int idx = tid; idx < 8 * 33; idx += 256) {   // v with ones padding
            int si = idx / 33, e = idx % 33;
            int s = s0 + si;
            float vv = 0.f;
            if (s < SSEQ) vv = (e < 32) ? qkvb[(long long)s * (3 * DD) + 2 * DD + h * 32 + e] : 1.f;
            vs[si][e] = vv;
        }
        __syncthreads();
#pragma unroll
        for (int si = 0; si < 8; si++) {
#pragma unroll
            for (int r = 0; r < 5; r++) {
                int f = tid + (r << 8);
                if (f < 1056) acc[r] += vs[si][f >> 5] * ks[si][f & 31];
            }
        }
        __syncthreads();
    }
#pragma unroll
    for (int r = 0; r < 5; r++) {
        int f = tid + (r << 8);
        if (f < 1056) vk[f] = acc[r];
    }
    __syncthreads();

    for (int s = tid; s < SSEQ; s += 256) {
        float q[32];
        const float* qp = qkvb + (long long)s * (3 * DD) + h * 32;
#pragma unroll
        for (int d4 = 0; d4 < 32; d4 += 4) {
            float4 qv = *(const float4*)(qp + d4);
            q[d4 + 0] = fmaxf(qv.x, 0.f); q[d4 + 1] = fmaxf(qv.y, 0.f);
            q[d4 + 2] = fmaxf(qv.z, 0.f); q[d4 + 3] = fmaxf(qv.w, 0.f);
        }
        float den = 0.f;
#pragma unroll
        for (int d = 0; d < 32; d++) den += vk[32 * 32 + d] * q[d];
        float inv = 1.0f / (den + 1e-8f);
        if (s >= 2) {
            float* op = attn + ((long long)(b * STOK + s - 2)) * DD + h * 32;
            for (int e = 0; e < 32; e++) {
                float num = 0.f;
#pragma unroll
                for (int d = 0; d < 32; d++) num += vk[e * 32 + d] * q[d];
                op[e] = num * inv;
            }
        }
    }
}

// ---------------- comb(a)*g_msa + residual -> x1 ----------------
__global__ void comb1_k(const float* __restrict__ x, const float* __restrict__ a,
                        const float* __restrict__ ss, float* __restrict__ x1)
{
    long long gid = (long long)blockIdx.x * blockDim.x + threadIdx.x;
    if (gid >= (long long)BN * SN) return;
    int hw = (int)(gid % HWSZ);
    int c = (int)((gid / HWSZ) % CCH);
    int b = (int)(gid / SN);
    int hh = hw >> 6, ww = hw & 63;
    int t = ((hh >> 1) << 5) + (ww >> 1);
    int j = (c << 2) + ((hh & 1) << 1) + (ww & 1);
    float g = ss[((long long)b * SIXC + 576 + c) * HWSZ + hw];
    x1[gid] = x[gid] + a[((long long)(b * STOK + t)) * DD + j] * g;
}

// ---------------- MLP modulate + segment (transposed): t2T[b][j][n] ----------------
__global__ void mlp_segT_k(const float* __restrict__ x1, const float* __restrict__ ss,
                           const float* __restrict__ stats, float* __restrict__ t2T)
{
    long long gid = (long long)blockIdx.x * blockDim.x + threadIdx.x;
    if (gid >= (long long)BN * DD * STOK) return;
    int n = (int)(gid % STOK);
    int j = (int)((gid / STOK) % DD);
    int b = (int)(gid / ((long long)DD * STOK));
    int c = j >> 2, p1 = (j >> 1) & 1, p2 = j & 1;
    int n1 = n >> 5, n2 = n & 31;
    int hw = ((2 * n1 + p1) << 6) + 2 * n2 + p2;
    float mu = stats[b * 2], rsig = stats[b * 2 + 1];
    float xv = x1[((long long)b * CCH + c) * HWSZ + hw];
    float sc = ss[((long long)b * SIXC + 1152 + c) * HWSZ + hw];
    float sh = ss[((long long)b * SIXC + 864 + c) * HWSZ + hw];
    t2T[gid] = (xv - mu) * rsig * (1.f + sc) + sh;
}

// ---------------- depthwise 3x3 + GLU gate ----------------
__global__ void dwglu_k(const float* __restrict__ hexp, const float* __restrict__ dw_w,
                        const float* __restrict__ dw_b, float* __restrict__ hglu)
{
    long long gid = (long long)blockIdx.x * blockDim.x + threadIdx.x;
    if (gid >= (long long)BN * HFF * STOK) return;
    int n = (int)(gid % STOK);
    int ch = (int)((gid / STOK) % HFF);
    int b = (int)(gid / ((long long)HFF * STOK));
    int y = n >> 5, xx = n & 31;
    const float* pa = hexp + ((long long)b * HF2 + ch) * STOK;
    const float* pg = hexp + ((long long)b * HF2 + ch + HFF) * STOK;
    const float* wa = dw_w + ch * 9;
    const float* wg = dw_w + (ch + HFF) * 9;
    float va = dw_b[ch], vg = dw_b[ch + HFF];
#pragma unroll
    for (int ky = -1; ky <= 1; ky++) {
        int yy = y + ky;
        if ((unsigned)yy >= 32u) continue;
#pragma unroll
        for (int kx = -1; kx <= 1; kx++) {
            int xc = xx + kx;
            if ((unsigned)xc >= 32u) continue;
            int nn = (yy << 5) + xc;
            int wi = (ky + 1) * 3 + (kx + 1);
            va += wa[wi] * pa[nn];
            vg += wg[wi] * pg[nn];
        }
    }
    hglu[gid] = va * siluf(vg);
}

// ---------------- comb(m)*g_mlp + residual -> out ----------------
__global__ void comb2_k(const float* __restrict__ x1, const float* __restrict__ mT,
                        const float* __restrict__ ss, float* __restrict__ out)
{
    long long gid = (long long)blockIdx.x * blockDim.x + threadIdx.x;
    if (gid >= (long long)BN * SN) return;
    int hw = (int)(gid % HWSZ);
    int c = (int)((gid / HWSZ) % CCH);
    int b = (int)(gid / SN);
    int hh = hw >> 6, ww = hw & 63;
    int t = ((hh >> 1) << 5) + (ww >> 1);
    int j = (c << 2) + ((hh & 1) << 1) + (ww & 1);
    float g = ss[((long long)b * SIXC + 1440 + c) * HWSZ + hw];
    out[gid] = x1[gid] + mT[((long long)b * DD + j) * STOK + t] * g;
}

// ---------------- launch ----------------
extern "C" void kernel_launch(void* const* d_in, const int* in_sizes, int n_in,
                              void* d_out, int out_size)
{
    const float* x      = (const float*)d_in[0];
    const float* cond   = (const float*)d_in[1];
    const float* gtok   = (const float*)d_in[2];
    const float* ttok   = (const float*)d_in[3];
    const float* ss_w   = (const float*)d_in[4];
    const float* ss_b   = (const float*)d_in[5];
    const float* qkv_w  = (const float*)d_in[6];
    const float* proj_w = (const float*)d_in[7];
    const float* proj_b = (const float*)d_in[8];
    const float* inv_w  = (const float*)d_in[9];
    const float* inv_b  = (const float*)d_in[10];
    const float* dw_w   = (const float*)d_in[11];
    const float* dw_b   = (const float*)d_in[12];
    const float* pw_w   = (const float*)d_in[13];
    float* out = (float*)d_out;

    float *p_ss, *p_tok, *p_qkv, *p_attn, *p_aproj, *p_x1, *p_t2T, *p_hexp, *p_hglu, *p_mT,
          *p_psum, *p_psumsq, *p_stats;
    cudaGetSymbolAddress((void**)&p_ss, g_ss);
    cudaGetSymbolAddress((void**)&p_tok, g_tok);
    cudaGetSymbolAddress((void**)&p_qkv, g_qkv);
    cudaGetSymbolAddress((void**)&p_attn, g_attn);
    cudaGetSymbolAddress((void**)&p_aproj, g_aproj);
    cudaGetSymbolAddress((void**)&p_x1, g_x1);
    cudaGetSymbolAddress((void**)&p_t2T, g_t2T);
    cudaGetSymbolAddress((void**)&p_hexp, g_hexp);
    cudaGetSymbolAddress((void**)&p_hglu, g_hglu);
    cudaGetSymbolAddress((void**)&p_mT, g_mT);
    cudaGetSymbolAddress((void**)&p_psum, g_psum);
    cudaGetSymbolAddress((void**)&p_psumsq, g_psumsq);
    cudaGetSymbolAddress((void**)&p_stats, g_stats);

    // 1) scale_shift: per-batch  ss[b] = ss_w @ silu(cond[b]) + ss_b
    gemm_tc<false, true, 1, false><<<dim3(HWSZ / 128, (SIXC + 127) / 128, BN), 256>>>(
        ss_w, cond, p_ss, ss_b, SIXC, HWSZ, SIXC,
        (long long)SIXC * HWSZ, (long long)SIXC * HWSZ);

    // 2) LayerNorm(x)
    ln_partial_k<<<dim3(LNB, BN), 256>>>(x, p_psum, p_psumsq);
    ln_final_k<<<BN, 256>>>(p_psum, p_psumsq, p_stats);

    // 3) tokens
    tokinit_k<<<(BN * DD + 255) / 256, 256>>>(gtok, ttok, p_tok);
    msa_seg_k<<<(int)(((long long)BN * STOK * DD + 255) / 256), 256>>>(x, p_ss, p_stats, p_tok);

    // 4) qkv = tok @ qkv_w^T
    gemm_tc<true, false, 0, false><<<dim3((3 * DD) / 128, (BN * SSEQ + 127) / 128, 1), 256>>>(
        p_tok, qkv_w, p_qkv, nullptr, BN * SSEQ, 3 * DD, DD, 0, 0);

    // 5) linear attention
    attn_k<<<dim3(NHEADS, BN), 256>>>(p_qkv, p_attn);

    // 6) proj (tokens 2.. only) = attn @ proj_w^T + proj_b
    gemm_tc<true, false, 2, false><<<dim3(DD / 128, (BN * STOK) / 128, 1), 256>>>(
        p_attn, proj_w, p_aproj, proj_b, BN * STOK, DD, DD, 0, 0);

    // 7) x1 = x + comb(a)*g_msa
    comb1_k<<<(int)(((long long)BN * SN + 255) / 256), 256>>>(x, p_aproj, p_ss, p_x1);

    // 8) LayerNorm(x1)
    ln_partial_k<<<dim3(LNB, BN), 256>>>(p_x1, p_psum, p_psumsq);
    ln_final_k<<<BN, 256>>>(p_psum, p_psumsq, p_stats);

    // 9) MLP modulate+segment (transposed layout)
    mlp_segT_k<<<(int)(((long long)BN * DD * STOK + 255) / 256), 256>>>(p_x1, p_ss, p_stats, p_t2T);

    // 10) expand: hexp[b] = silu(inv_w @ t2T[b] + inv_b)
    gemm_tc<false, false, 1, true><<<dim3(STOK / 128, HF2 / 128, BN), 256>>>(
        inv_w, p_t2T, p_hexp, inv_b, HF2, STOK, DD,
        (long long)DD * STOK, (long long)HF2 * STOK);

    // 11) depthwise 3x3 + GLU
    dwglu_k<<<(int)(((long long)BN * HFF * STOK + 255) / 256), 256>>>(p_hexp, dw_w, dw_b, p_hglu);

    // 12) project: mT[b] = pw_w @ hglu[b]
    gemm_tc<false, false, 0, false><<<dim3(STOK / 128, DD / 128, BN), 256>>>(
        pw_w, p_hglu, p_mT, nullptr, DD, STOK, HFF,
        (long long)HFF * STOK, (long long)DD * STOK);

    // 13) out = x1 + comb(m)*g_mlp
    comb2_k<<<(int)(((long long)BN * SN + 255) / 256), 256>>>(p_x1, p_mT, p_ss, out);
}

// round 3
// speedup vs baseline: 3.5802x; 1.6155x over previous
#include <cuda_runtime.h>
#include <cuda_bf16.h>

// ---------------- problem constants ----------------
#define BN     4
#define CCH    288
#define HWSZ   4096            // 64*64
#define SN     (CCH*HWSZ)      // 1179648 per-sample elements
#define DD     1152
#define SIXC   1728
#define STOK   1024            // spatial tokens (32x32)
#define SSEQ   1026            // + global + time
#define NHEADS 36
#define HFF    4608
#define HF2    9216
#define LNB    144             // ln partial blocks per sample

// ---------------- scratch (static device memory; no allocations) ----------------
__device__ float g_ss   [BN*SIXC*HWSZ];
__device__ float g_tok  [BN*SSEQ*DD];
__device__ float g_qkv  [BN*SSEQ*3*DD];
__device__ float g_attn [BN*STOK*DD];
__device__ float g_aproj[BN*STOK*DD];
__device__ float g_x1   [BN*SN];
__device__ float g_t2T  [BN*DD*STOK];
__device__ float g_hexp [BN*HF2*STOK];
__device__ float g_hglu [BN*HFF*STOK];
__device__ float g_mT   [BN*DD*STOK];
__device__ float g_psum [BN*LNB];
__device__ float g_psumsq[BN*LNB];
__device__ float g_stats[BN*2];

__device__ __forceinline__ float siluf(float v) { return v / (1.0f + __expf(-v)); }

__device__ __forceinline__ unsigned pk2(float x, float y) {
    __nv_bfloat162 h = __floats2bfloat162_rn(x, y);
    return *reinterpret_cast<unsigned*>(&h);
}

__device__ __forceinline__ void ldsm4(unsigned r[4], unsigned addr) {
    asm volatile("ldmatrix.sync.aligned.m8n8.x4.shared.b16 {%0,%1,%2,%3}, [%4];"
                 : "=r"(r[0]), "=r"(r[1]), "=r"(r[2]), "=r"(r[3]) : "r"(addr));
}
__device__ __forceinline__ void ldsm4t(unsigned r[4], unsigned addr) {
    asm volatile("ldmatrix.sync.aligned.m8n8.x4.trans.shared.b16 {%0,%1,%2,%3}, [%4];"
                 : "=r"(r[0]), "=r"(r[1]), "=r"(r[2]), "=r"(r[3]) : "r"(addr));
}
__device__ __forceinline__ void mma_bf16(float c[4], const unsigned a[4], unsigned b0, unsigned b1) {
    asm volatile(
        "mma.sync.aligned.m16n8k16.row.col.f32.bf16.bf16.f32 "
        "{%0,%1,%2,%3}, {%4,%5,%6,%7}, {%8,%9}, {%0,%1,%2,%3};"
        : "+f"(c[0]), "+f"(c[1]), "+f"(c[2]), "+f"(c[3])
        : "r"(a[0]), "r"(a[1]), "r"(a[2]), "r"(a[3]), "r"(b0), "r"(b1));
}

// ---------------- bf16 tensor-core GEMM (double-buffered, ldmatrix) ----------------
// C[M,N] = A[M,K] * op(B); TRANSB=false: B[K,N]; true: B[N,K] (C = A*B^T).
// Requires N % 128 == 0, K % 32 == 0 (all call sites comply); M guarded.
// blockIdx.z batches B and C. BIASMODE: 0 none, 1 bias[m], 2 bias[n].
template<bool TRANSB, bool B_SILU, int BIASMODE, bool ACT_SILU>
__global__ __launch_bounds__(256)
void gemm_bf(const float* __restrict__ A, const float* __restrict__ B,
             float* __restrict__ C, const float* __restrict__ bias,
             int M, int N, int K, long long strideB, long long strideC)
{
    // stage size 8KB each for A and B tiles (128x32 bf16 or 32x128 bf16)
    __shared__ __align__(16) unsigned char smem[4 * 8192];
    const unsigned sbase = (unsigned)__cvta_generic_to_shared(smem);

    const float* Bz = B + (long long)blockIdx.z * strideB;
    float*       Cz = C + (long long)blockIdx.z * strideC;

    const int tid  = threadIdx.x;
    const int lane = tid & 31;
    const int warp = tid >> 5;
    const int wm   = (warp & 3) * 32;
    const int wn   = (warp >> 2) * 64;
    const int row0 = blockIdx.y * 128;
    const int col0 = blockIdx.x * 128;

    float acc[2][8][4];
#pragma unroll
    for (int i = 0; i < 2; i++)
#pragma unroll
        for (int j = 0; j < 8; j++)
#pragma unroll
            for (int r = 0; r < 4; r++) acc[i][j][r] = 0.f;

    float4 ar[4], br[4];

    // ---- global loads into regs for tile at k0
    auto loadA = [&](int k0) {
#pragma unroll
        for (int i = 0; i < 2; i++) {
            int f = tid + (i << 8);
            int row = f >> 2, ch = f & 3;
            float4 z = make_float4(0.f, 0.f, 0.f, 0.f);
            ar[2 * i] = z; ar[2 * i + 1] = z;
            if (row0 + row < M) {
                const float* p = A + (long long)(row0 + row) * K + k0 + ch * 8;
                ar[2 * i]     = *(const float4*)(p);
                ar[2 * i + 1] = *(const float4*)(p + 4);
            }
        }
    };
    auto loadB = [&](int k0) {
#pragma unroll
        for (int i = 0; i < 2; i++) {
            int f = tid + (i << 8);
            const float* p;
            if (TRANSB) {
                int n = f >> 2, ch = f & 3;
                p = Bz + (long long)(col0 + n) * K + k0 + ch * 8;
            } else {
                int k = f >> 4, ch = f & 15;
                p = Bz + (long long)(k0 + k) * N + col0 + ch * 8;
            }
            float4 v0 = *(const float4*)(p);
            float4 v1 = *(const float4*)(p + 4);
            if (B_SILU) {
                v0.x = siluf(v0.x); v0.y = siluf(v0.y); v0.z = siluf(v0.z); v0.w = siluf(v0.w);
                v1.x = siluf(v1.x); v1.y = siluf(v1.y); v1.z = siluf(v1.z); v1.w = siluf(v1.w);
            }
            br[2 * i] = v0; br[2 * i + 1] = v1;
        }
    };
    // ---- convert + store regs into smem stage
    auto storeA = [&](int st) {
        unsigned base = st * 8192u;
#pragma unroll
        for (int i = 0; i < 2; i++) {
            int f = tid + (i << 8);
            int row = f >> 2, ch = f & 3;
            uint4 v;
            v.x = pk2(ar[2 * i].x,     ar[2 * i].y);
            v.y = pk2(ar[2 * i].z,     ar[2 * i].w);
            v.z = pk2(ar[2 * i + 1].x, ar[2 * i + 1].y);
            v.w = pk2(ar[2 * i + 1].z, ar[2 * i + 1].w);
            unsigned off = base + row * 64u + (unsigned)((ch ^ ((row >> 1) & 3)) << 4);
            *(uint4*)(smem + off) = v;
        }
    };
    auto storeB = [&](int st) {
        unsigned base = 16384u + st * 8192u;
#pragma unroll
        for (int i = 0; i < 2; i++) {
            int f = tid + (i << 8);
            uint4 v;
            v.x = pk2(br[2 * i].x,     br[2 * i].y);
            v.y = pk2(br[2 * i].z,     br[2 * i].w);
            v.z = pk2(br[2 * i + 1].x, br[2 * i + 1].y);
            v.w = pk2(br[2 * i + 1].z, br[2 * i + 1].w);
            unsigned off;
            if (TRANSB) {
                int n = f >> 2, ch = f & 3;
                off = base + n * 64u + (unsigned)((ch ^ ((n >> 1) & 3)) << 4);
            } else {
                int k = f >> 4, ch = f & 15;
                off = base + k * 256u + (unsigned)((ch ^ (k & 7)) << 4);
            }
            *(uint4*)(smem + off) = v;
        }
    };

    // ---- prologue
    loadA(0); loadB(0);
    storeA(0); storeB(0);
    __syncthreads();

    int stage = 0;
    for (int k0 = 0; k0 < K; k0 += 32) {
        bool has = (k0 + 32) < K;
        if (has) { loadA(k0 + 32); loadB(k0 + 32); }

        unsigned sA = sbase + stage * 8192u;
        unsigned sB = sbase + 16384u + stage * 8192u;

#pragma unroll
        for (int kk = 0; kk < 32; kk += 16) {
            unsigned a_fr[2][4];
#pragma unroll
            for (int i = 0; i < 2; i++) {
                int row = wm + 16 * i + (lane & 15);
                int ch  = (kk >> 3) + (lane >> 4);
                unsigned addr = sA + row * 64u + (unsigned)((ch ^ ((row >> 1) & 3)) << 4);
                ldsm4(a_fr[i], addr);
            }
            unsigned b_fr[4][4];
#pragma unroll
            for (int j = 0; j < 4; j++) {
                if (TRANSB) {
                    int row = wn + 16 * j + ((lane >> 4) << 3) + (lane & 7);
                    int ch  = (kk >> 3) + ((lane >> 3) & 1);
                    unsigned addr = sB + row * 64u + (unsigned)((ch ^ ((row >> 1) & 3)) << 4);
                    ldsm4(b_fr[j], addr);
                } else {
                    int g   = lane >> 3;
                    int row = kk + ((g & 1) << 3) + (lane & 7);
                    int ch  = ((wn + 16 * j) >> 3) + (g >> 1);
                    unsigned addr = sB + row * 256u + (unsigned)((ch ^ (row & 7)) << 4);
                    ldsm4t(b_fr[j], addr);
                }
            }
#pragma unroll
            for (int i = 0; i < 2; i++)
#pragma unroll
                for (int j = 0; j < 4; j++) {
                    mma_bf16(acc[i][2 * j],     a_fr[i], b_fr[j][0], b_fr[j][1]);
                    mma_bf16(acc[i][2 * j + 1], a_fr[i], b_fr[j][2], b_fr[j][3]);
                }
        }

        if (has) { storeA(stage ^ 1); storeB(stage ^ 1); }
        __syncthreads();
        stage ^= 1;
    }

    // ---- epilogue
#pragma unroll
    for (int i = 0; i < 2; i++) {
        const int gid = lane >> 2, tig = lane & 3;
#pragma unroll
        for (int rr = 0; rr < 2; rr++) {
            int r = row0 + wm + i * 16 + gid + rr * 8;
            if (r >= M) continue;
            float bm = (BIASMODE == 1) ? bias[r] : 0.f;
#pragma unroll
            for (int j = 0; j < 8; j++) {
                int cc = col0 + wn + j * 8 + 2 * tig;
                float x0 = acc[i][j][2 * rr + 0];
                float x1 = acc[i][j][2 * rr + 1];
                if (BIASMODE == 1) { x0 += bm; x1 += bm; }
                if (BIASMODE == 2) { x0 += bias[cc]; x1 += bias[cc + 1]; }
                if (ACT_SILU) { x0 = siluf(x0); x1 = siluf(x1); }
                *(float2*)(Cz + (long long)r * N + cc) = make_float2(x0, x1);
            }
        }
    }
}

// ---------------- LayerNorm (whole-sample) reduction ----------------
__global__ void ln_partial_k(const float* __restrict__ x,
                             float* __restrict__ psum, float* __restrict__ psumsq)
{
    int b = blockIdx.y;
    const float* xb = x + (long long)b * SN;
    const int chunk = SN / LNB;
    int base = blockIdx.x * chunk;
    float s = 0.f, sq = 0.f;
    for (int i = base + threadIdx.x; i < base + chunk; i += 256) {
        float v = xb[i]; s += v; sq += v * v;
    }
    __shared__ float sh1[256], sh2[256];
    sh1[threadIdx.x] = s; sh2[threadIdx.x] = sq;
    __syncthreads();
    for (int o = 128; o > 0; o >>= 1) {
        if (threadIdx.x < o) {
            sh1[threadIdx.x] += sh1[threadIdx.x + o];
            sh2[threadIdx.x] += sh2[threadIdx.x + o];
        }
        __syncthreads();
    }
    if (threadIdx.x == 0) {
        psum[b * LNB + blockIdx.x] = sh1[0];
        psumsq[b * LNB + blockIdx.x] = sh2[0];
    }
}

__global__ void ln_final_k(const float* __restrict__ psum, const float* __restrict__ psumsq,
                           float* __restrict__ stats)
{
    int b = blockIdx.x;
    float s = 0.f, sq = 0.f;
    for (int i = threadIdx.x; i < LNB; i += 256) { s += psum[b * LNB + i]; sq += psumsq[b * LNB + i]; }
    __shared__ float sh1[256], sh2[256];
    sh1[threadIdx.x] = s; sh2[threadIdx.x] = sq;
    __syncthreads();
    for (int o = 128; o > 0; o >>= 1) {
        if (threadIdx.x < o) {
            sh1[threadIdx.x] += sh1[threadIdx.x + o];
            sh2[threadIdx.x] += sh2[threadIdx.x + o];
        }
        __syncthreads();
    }
    if (threadIdx.x == 0) {
        float mu = sh1[0] / (float)SN;
        float var = sh2[0] / (float)SN - mu * mu;
        stats[b * 2 + 0] = mu;
        stats[b * 2 + 1] = rsqrtf(var + 1e-6f);
    }
}

// ---------------- token init ----------------
__global__ void tokinit_k(const float* __restrict__ gt, const float* __restrict__ tt,
                          float* __restrict__ tok)
{
    int gid = blockIdx.x * blockDim.x + threadIdx.x;
    if (gid >= BN * DD) return;
    int b = gid / DD, j = gid % DD;
    tok[((long long)b * SSEQ + 0) * DD + j] = gt[b * DD + j];
    tok[((long long)b * SSEQ + 1) * DD + j] = tt[b * DD + j];
}

// ---------------- MSA modulate + segment ----------------
__global__ void msa_seg_k(const float* __restrict__ x, const float* __restrict__ ss,
                          const float* __restrict__ stats, float* __restrict__ tok)
{
    long long gid = (long long)blockIdx.x * blockDim.x + threadIdx.x;
    if (gid >= (long long)BN * STOK * DD) return;
    int j = (int)(gid % DD);
    int t = (int)((gid / DD) % STOK);
    int b = (int)(gid / ((long long)STOK * DD));
    int c = j >> 2, p1 = (j >> 1) & 1, p2 = j & 1;
    int n1 = t >> 5, n2 = t & 31;
    int hw = ((2 * n1 + p1) << 6) + 2 * n2 + p2;
    float mu = stats[b * 2], rsig = stats[b * 2 + 1];
    float xv = x[((long long)b * CCH + c) * HWSZ + hw];
    float sc = ss[((long long)b * SIXC + 288 + c) * HWSZ + hw];
    float sh = ss[((long long)b * SIXC + c) * HWSZ + hw];
    tok[((long long)b * SSEQ + 2 + t) * DD + j] = (xv - mu) * rsig * (1.f + sc) + sh;
}

// ---------------- linear attention ----------------
__global__ void attn_k(const float* __restrict__ qkv, float* __restrict__ attn)
{
    int h = blockIdx.x, b = blockIdx.y;
    int tid = threadIdx.x;
    __shared__ float vk[33 * 32];
    __shared__ float ks[8][32];
    __shared__ float vs[8][33];
    float acc[5] = {0.f, 0.f, 0.f, 0.f, 0.f};
    const float* qkvb = qkv + (long long)b * SSEQ * (3 * DD);

    for (int s0 = 0; s0 < SSEQ; s0 += 8) {
        {
            int si = tid >> 5, d = tid & 31;
            int s = s0 + si;
            ks[si][d] = (s < SSEQ) ? fmaxf(qkvb[(long long)s * (3 * DD) + DD + h * 32 + d], 0.f) : 0.f;
        }
        for (int idx = tid; idx < 8 * 33; idx += 256) {
            int si = idx / 33, e = idx % 33;
            int s = s0 + si;
            float vv = 0.f;
            if (s < SSEQ) vv = (e < 32) ? qkvb[(long long)s * (3 * DD) + 2 * DD + h * 32 + e] : 1.f;
            vs[si][e] = vv;
        }
        __syncthreads();
#pragma unroll
        for (int si = 0; si < 8; si++) {
#pragma unroll
            for (int r = 0; r < 5; r++) {
                int f = tid + (r << 8);
                if (f < 1056) acc[r] += vs[si][f >> 5] * ks[si][f & 31];
            }
        }
        __syncthreads();
    }
#pragma unroll
    for (int r = 0; r < 5; r++) {
        int f = tid + (r << 8);
        if (f < 1056) vk[f] = acc[r];
    }
    __syncthreads();

    for (int s = tid; s < SSEQ; s += 256) {
        float q[32];
        const float* qp = qkvb + (long long)s * (3 * DD) + h * 32;
#pragma unroll
        for (int d4 = 0; d4 < 32; d4 += 4) {
            float4 qv = *(const float4*)(qp + d4);
            q[d4 + 0] = fmaxf(qv.x, 0.f); q[d4 + 1] = fmaxf(qv.y, 0.f);
            q[d4 + 2] = fmaxf(qv.z, 0.f); q[d4 + 3] = fmaxf(qv.w, 0.f);
        }
        float den = 0.f;
#pragma unroll
        for (int d = 0; d < 32; d++) den += vk[32 * 32 + d] * q[d];
        float inv = 1.0f / (den + 1e-8f);
        if (s >= 2) {
            float* op = attn + ((long long)(b * STOK + s - 2)) * DD + h * 32;
            for (int e = 0; e < 32; e++) {
                float num = 0.f;
#pragma unroll
                for (int d = 0; d < 32; d++) num += vk[e * 32 + d] * q[d];
                op[e] = num * inv;
            }
        }
    }
}

// ---------------- comb(a)*g_msa + residual -> x1 ----------------
__global__ void comb1_k(const float* __restrict__ x, const float* __restrict__ a,
                        const float* __restrict__ ss, float* __restrict__ x1)
{
    long long gid = (long long)blockIdx.x * blockDim.x + threadIdx.x;
    if (gid >= (long long)BN * SN) return;
    int hw = (int)(gid % HWSZ);
    int c = (int)((gid / HWSZ) % CCH);
    int b = (int)(gid / SN);
    int hh = hw >> 6, ww = hw & 63;
    int t = ((hh >> 1) << 5) + (ww >> 1);
    int j = (c << 2) + ((hh & 1) << 1) + (ww & 1);
    float g = ss[((long long)b * SIXC + 576 + c) * HWSZ + hw];
    x1[gid] = x[gid] + a[((long long)(b * STOK + t)) * DD + j] * g;
}

// ---------------- MLP modulate + segment (transposed) ----------------
__global__ void mlp_segT_k(const float* __restrict__ x1, const float* __restrict__ ss,
                           const float* __restrict__ stats, float* __restrict__ t2T)
{
    long long gid = (long long)blockIdx.x * blockDim.x + threadIdx.x;
    if (gid >= (long long)BN * DD * STOK) return;
    int n = (int)(gid % STOK);
    int j = (int)((gid / STOK) % DD);
    int b = (int)(gid / ((long long)DD * STOK));
    int c = j >> 2, p1 = (j >> 1) & 1, p2 = j & 1;
    int n1 = n >> 5, n2 = n & 31;
    int hw = ((2 * n1 + p1) << 6) + 2 * n2 + p2;
    float mu = stats[b * 2], rsig = stats[b * 2 + 1];
    float xv = x1[((long long)b * CCH + c) * HWSZ + hw];
    float sc = ss[((long long)b * SIXC + 1152 + c) * HWSZ + hw];
    float sh = ss[((long long)b * SIXC + 864 + c) * HWSZ + hw];
    t2T[gid] = (xv - mu) * rsig * (1.f + sc) + sh;
}

// ---------------- depthwise 3x3 + GLU ----------------
__global__ void dwglu_k(const float* __restrict__ hexp, const float* __restrict__ dw_w,
                        const float* __restrict__ dw_b, float* __restrict__ hglu)
{
    long long gid = (long long)blockIdx.x * blockDim.x + threadIdx.x;
    if (gid >= (long long)BN * HFF * STOK) return;
    int n = (int)(gid % STOK);
    int ch = (int)((gid / STOK) % HFF);
    int b = (int)(gid / ((long long)HFF * STOK));
    int y = n >> 5, xx = n & 31;
    const float* pa = hexp + ((long long)b * HF2 + ch) * STOK;
    const float* pg = hexp + ((long long)b * HF2 + ch + HFF) * STOK;
    const float* wa = dw_w + ch * 9;
    const float* wg = dw_w + (ch + HFF) * 9;
    float va = dw_b[ch], vg = dw_b[ch + HFF];
#pragma unroll
    for (int ky = -1; ky <= 1; ky++) {
        int yy = y + ky;
        if ((unsigned)yy >= 32u) continue;
#pragma unroll
        for (int kx = -1; kx <= 1; kx++) {
            int xc = xx + kx;
            if ((unsigned)xc >= 32u) continue;
            int nn = (yy << 5) + xc;
            int wi = (ky + 1) * 3 + (kx + 1);
            va += wa[wi] * pa[nn];
            vg += wg[wi] * pg[nn];
        }
    }
    hglu[gid] = va * siluf(vg);
}

// ---------------- comb(m)*g_mlp + residual -> out ----------------
__global__ void comb2_k(const float* __restrict__ x1, const float* __restrict__ mT,
                        const float* __restrict__ ss, float* __restrict__ out)
{
    long long gid = (long long)blockIdx.x * blockDim.x + threadIdx.x;
    if (gid >= (long long)BN * SN) return;
    int hw = (int)(gid % HWSZ);
    int c = (int)((gid / HWSZ) % CCH);
    int b = (int)(gid / SN);
    int hh = hw >> 6, ww = hw & 63;
    int t = ((hh >> 1) << 5) + (ww >> 1);
    int j = (c << 2) + ((hh & 1) << 1) + (ww & 1);
    float g = ss[((long long)b * SIXC + 1440 + c) * HWSZ + hw];
    out[gid] = x1[gid] + mT[((long long)b * DD + j) * STOK + t] * g;
}

// ---------------- launch ----------------
extern "C" void kernel_launch(void* const* d_in, const int* in_sizes, int n_in,
                              void* d_out, int out_size)
{
    const float* x      = (const float*)d_in[0];
    const float* cond   = (const float*)d_in[1];
    const float* gtok   = (const float*)d_in[2];
    const float* ttok   = (const float*)d_in[3];
    const float* ss_w   = (const float*)d_in[4];
    const float* ss_b   = (const float*)d_in[5];
    const float* qkv_w  = (const float*)d_in[6];
    const float* proj_w = (const float*)d_in[7];
    const float* proj_b = (const float*)d_in[8];
    const float* inv_w  = (const float*)d_in[9];
    const float* inv_b  = (const float*)d_in[10];
    const float* dw_w   = (const float*)d_in[11];
    const float* dw_b   = (const float*)d_in[12];
    const float* pw_w   = (const float*)d_in[13];
    float* out = (float*)d_out;

    float *p_ss, *p_tok, *p_qkv, *p_attn, *p_aproj, *p_x1, *p_t2T, *p_hexp, *p_hglu, *p_mT,
          *p_psum, *p_psumsq, *p_stats;
    cudaGetSymbolAddress((void**)&p_ss, g_ss);
    cudaGetSymbolAddress((void**)&p_tok, g_tok);
    cudaGetSymbolAddress((void**)&p_qkv, g_qkv);
    cudaGetSymbolAddress((void**)&p_attn, g_attn);
    cudaGetSymbolAddress((void**)&p_aproj, g_aproj);
    cudaGetSymbolAddress((void**)&p_x1, g_x1);
    cudaGetSymbolAddress((void**)&p_t2T, g_t2T);
    cudaGetSymbolAddress((void**)&p_hexp, g_hexp);
    cudaGetSymbolAddress((void**)&p_hglu, g_hglu);
    cudaGetSymbolAddress((void**)&p_mT, g_mT);
    cudaGetSymbolAddress((void**)&p_psum, g_psum);
    cudaGetSymbolAddress((void**)&p_psumsq, g_psumsq);
    cudaGetSymbolAddress((void**)&p_stats, g_stats);

    // 1) scale_shift: ss[b] = ss_w @ silu(cond[b]) + ss_b
    gemm_bf<false, true, 1, false><<<dim3(HWSZ / 128, (SIXC + 127) / 128, BN), 256>>>(
        ss_w, cond, p_ss, ss_b, SIXC, HWSZ, SIXC,
        (long long)SIXC * HWSZ, (long long)SIXC * HWSZ);

    // 2) LayerNorm(x)
    ln_partial_k<<<dim3(LNB, BN), 256>>>(x, p_psum, p_psumsq);
    ln_final_k<<<BN, 256>>>(p_psum, p_psumsq, p_stats);

    // 3) tokens
    tokinit_k<<<(BN * DD + 255) / 256, 256>>>(gtok, ttok, p_tok);
    msa_seg_k<<<(int)(((long long)BN * STOK * DD + 255) / 256), 256>>>(x, p_ss, p_stats, p_tok);

    // 4) qkv = tok @ qkv_w^T
    gemm_bf<true, false, 0, false><<<dim3((3 * DD) / 128, (BN * SSEQ + 127) / 128, 1), 256>>>(
        p_tok, qkv_w, p_qkv, nullptr, BN * SSEQ, 3 * DD, DD, 0, 0);

    // 5) linear attention
    attn_k<<<dim3(NHEADS, BN), 256>>>(p_qkv, p_attn);

    // 6) proj = attn @ proj_w^T + proj_b
    gemm_bf<true, false, 2, false><<<dim3(DD / 128, (BN * STOK) / 128, 1), 256>>>(
        p_attn, proj_w, p_aproj, proj_b, BN * STOK, DD, DD, 0, 0);

    // 7) x1 = x + comb(a)*g_msa
    comb1_k<<<(int)(((long long)BN * SN + 255) / 256), 256>>>(x, p_aproj, p_ss, p_x1);

    // 8) LayerNorm(x1)
    ln_partial_k<<<dim3(LNB, BN), 256>>>(p_x1, p_psum, p_psumsq);
    ln_final_k<<<BN, 256>>>(p_psum, p_psumsq, p_stats);

    // 9) MLP modulate+segment (transposed layout)
    mlp_segT_k<<<(int)(((long long)BN * DD * STOK + 255) / 256), 256>>>(p_x1, p_ss, p_stats, p_t2T);

    // 10) expand: hexp[b] = silu(inv_w @ t2T[b] + inv_b)
    gemm_bf<false, false, 1, true><<<dim3(STOK / 128, HF2 / 128, BN), 256>>>(
        inv_w, p_t2T, p_hexp, inv_b, HF2, STOK, DD,
        (long long)DD * STOK, (long long)HF2 * STOK);

    // 11) depthwise 3x3 + GLU
    dwglu_k<<<(int)(((long long)BN * HFF * STOK + 255) / 256), 256>>>(p_hexp, dw_w, dw_b, p_hglu);

    // 12) project: mT[b] = pw_w @ hglu[b]
    gemm_bf<false, false, 0, false><<<dim3(STOK / 128, DD / 128, BN), 256>>>(
        pw_w, p_hglu, p_mT, nullptr, DD, STOK, HFF,
        (long long)HFF * STOK, (long long)DD * STOK);

    // 13) out = x1 + comb(m)*g_mlp
    comb2_k<<<(int)(((long long)BN * SN + 255) / 256), 256>>>(p_x1, p_mT, p_ss, out);
}

// round 4
// speedup vs baseline: 5.5427x; 1.5482x over previous
#include <cuda_runtime.h>
#include <cuda_bf16.h>

// ---------------- problem constants ----------------
#define BN     4
#define CCH    288
#define HWSZ   4096
#define SN     (CCH*HWSZ)
#define DD     1152
#define SIXC   1728
#define STOK   1024
#define SSEQ   1026
#define NHEADS 36
#define HFF    4608
#define HF2    9216
#define LNB    144

typedef __nv_bfloat16 bf16;

// ---------------- scratch (static device memory) ----------------
__device__ float g_ss   [BN*SIXC*HWSZ];     // fp32 scale/shift maps
__device__ bf16  g_condb[BN*SIXC*HWSZ];     // silu(cond) in bf16
__device__ bf16  g_tok  [BN*SSEQ*DD];
__device__ float g_qkv  [BN*SSEQ*3*DD];
__device__ bf16  g_attn [BN*STOK*DD];
__device__ float g_aproj[BN*STOK*DD];
__device__ float g_x1   [BN*SN];
__device__ bf16  g_t2T  [BN*DD*STOK];
__device__ bf16  g_hexp [BN*HF2*STOK];
__device__ bf16  g_hglu [BN*HFF*STOK];
__device__ float g_mT   [BN*DD*STOK];
__device__ float g_psum [BN*LNB];
__device__ float g_psumsq[BN*LNB];
__device__ float g_stats[BN*2];
// bf16 weights
__device__ bf16  g_ssw  [SIXC*SIXC];
__device__ bf16  g_qkvw [3*DD*DD];
__device__ bf16  g_projw[DD*DD];
__device__ bf16  g_invw [HF2*DD];
__device__ bf16  g_pww  [DD*HFF];

__device__ __forceinline__ float siluf(float v) { return v / (1.0f + __expf(-v)); }

__device__ __forceinline__ void ldsm4(unsigned r[4], unsigned addr) {
    asm volatile("ldmatrix.sync.aligned.m8n8.x4.shared.b16 {%0,%1,%2,%3}, [%4];"
                 : "=r"(r[0]), "=r"(r[1]), "=r"(r[2]), "=r"(r[3]) : "r"(addr));
}
__device__ __forceinline__ void ldsm4t(unsigned r[4], unsigned addr) {
    asm volatile("ldmatrix.sync.aligned.m8n8.x4.trans.shared.b16 {%0,%1,%2,%3}, [%4];"
                 : "=r"(r[0]), "=r"(r[1]), "=r"(r[2]), "=r"(r[3]) : "r"(addr));
}
__device__ __forceinline__ void mma_bf16(float c[4], const unsigned a[4], unsigned b0, unsigned b1) {
    asm volatile(
        "mma.sync.aligned.m16n8k16.row.col.f32.bf16.bf16.f32 "
        "{%0,%1,%2,%3}, {%4,%5,%6,%7}, {%8,%9}, {%0,%1,%2,%3};"
        : "+f"(c[0]), "+f"(c[1]), "+f"(c[2]), "+f"(c[3])
        : "r"(a[0]), "r"(a[1]), "r"(a[2]), "r"(a[3]), "r"(b0), "r"(b1));
}
__device__ __forceinline__ void cpasync16(unsigned dst, const void* src, bool valid) {
    int sz = valid ? 16 : 0;
    asm volatile("cp.async.cg.shared.global [%0], [%1], 16, %2;" :: "r"(dst), "l"(src), "r"(sz));
}
__device__ __forceinline__ void cp_commit() { asm volatile("cp.async.commit_group;"); }
template<int N> __device__ __forceinline__ void cp_wait() {
    asm volatile("cp.async.wait_group %0;" :: "n"(N));
}

// ---------------- bf16 tensor-core GEMM: cp.async 3-stage pipeline ----------------
// C[M,N] = A[M,K] * op(B); TRANSB=false: B[K,N]; true: B[N,K].
// A,B bf16; C fp32 or bf16 (OUTBF). N%128==0, K%32==0; M guarded.
// blockIdx.z batches B and C. BIASMODE: 0 none, 1 bias[m], 2 bias[n].
template<bool TRANSB, int BIASMODE, bool ACT_SILU, bool OUTBF>
__global__ __launch_bounds__(256, 2)
void gemm_bf16(const bf16* __restrict__ A, const bf16* __restrict__ B,
               void* __restrict__ Cv, const float* __restrict__ bias,
               int M, int N, int K, long long strideB, long long strideC)
{
    __shared__ __align__(16) unsigned char smem[3 * 16384];   // 3 stages x (A 8KB + B 8KB)
    const unsigned sbase = (unsigned)__cvta_generic_to_shared(smem);

    const bf16* Bz = B + (long long)blockIdx.z * strideB;

    const int tid  = threadIdx.x;
    const int lane = tid & 31;
    const int warp = tid >> 5;
    const int wm   = (warp & 3) * 32;
    const int wn   = (warp >> 2) * 64;
    const int row0 = blockIdx.y * 128;
    const int col0 = blockIdx.x * 128;

    float acc[2][8][4];
#pragma unroll
    for (int i = 0; i < 2; i++)
#pragma unroll
        for (int j = 0; j < 8; j++)
#pragma unroll
            for (int r = 0; r < 4; r++) acc[i][j][r] = 0.f;

    const int nk = K / 32;

    auto copyStage = [&](int kt, int st) {
        int k0 = kt * 32;
        unsigned sA = sbase + st * 16384u;
        unsigned sB = sA + 8192u;
#pragma unroll
        for (int i = 0; i < 2; i++) {
            int f = tid + (i << 8);
            int row = f >> 2, ch = f & 3;
            unsigned dst = sA + row * 64u + (unsigned)((ch ^ ((row >> 1) & 3)) << 4);
            const bf16* src = A + (long long)(row0 + row) * K + k0 + ch * 8;
            cpasync16(dst, src, row0 + row < M);
        }
#pragma unroll
        for (int i = 0; i < 2; i++) {
            int f = tid + (i << 8);
            unsigned dst; const bf16* src;
            if (TRANSB) {
                int n = f >> 2, ch = f & 3;
                dst = sB + n * 64u + (unsigned)((ch ^ ((n >> 1) & 3)) << 4);
                src = Bz + (long long)(col0 + n) * K + k0 + ch * 8;
            } else {
                int k = f >> 4, ch = f & 15;
                dst = sB + k * 256u + (unsigned)((ch ^ (k & 7)) << 4);
                src = Bz + (long long)(k0 + k) * N + col0 + ch * 8;
            }
            cpasync16(dst, src, true);
        }
    };

    // prologue: 2 stages in flight
    copyStage(0, 0); cp_commit();
    if (nk > 1) copyStage(1, 1);
    cp_commit();

    for (int kt = 0; kt < nk; kt++) {
        cp_wait<1>();
        __syncthreads();

        int st = kt % 3;
        unsigned sA = sbase + st * 16384u;
        unsigned sB = sA + 8192u;

#pragma unroll
        for (int kk = 0; kk < 32; kk += 16) {
            unsigned a_fr[2][4];
#pragma unroll
            for (int i = 0; i < 2; i++) {
                int row = wm + 16 * i + (lane & 15);
                int ch  = (kk >> 3) + (lane >> 4);
                ldsm4(a_fr[i], sA + row * 64u + (unsigned)((ch ^ ((row >> 1) & 3)) << 4));
            }
            unsigned b_fr[4][4];
#pragma unroll
            for (int j = 0; j < 4; j++) {
                if (TRANSB) {
                    int row = wn + 16 * j + ((lane >> 4) << 3) + (lane & 7);
                    int ch  = (kk >> 3) + ((lane >> 3) & 1);
                    ldsm4(b_fr[j], sB + row * 64u + (unsigned)((ch ^ ((row >> 1) & 3)) << 4));
                } else {
                    int g   = lane >> 3;
                    int row = kk + ((g & 1) << 3) + (lane & 7);
                    int ch  = ((wn + 16 * j) >> 3) + (g >> 1);
                    ldsm4t(b_fr[j], sB + row * 256u + (unsigned)((ch ^ (row & 7)) << 4));
                }
            }
#pragma unroll
            for (int i = 0; i < 2; i++)
#pragma unroll
                for (int j = 0; j < 4; j++) {
                    mma_bf16(acc[i][2 * j],     a_fr[i], b_fr[j][0], b_fr[j][1]);
                    mma_bf16(acc[i][2 * j + 1], a_fr[i], b_fr[j][2], b_fr[j][3]);
                }
        }

        __syncthreads();
        if (kt + 2 < nk) copyStage(kt + 2, (kt + 2) % 3);
        cp_commit();
    }

    // ---- epilogue
    const int gid = lane >> 2, tig = lane & 3;
#pragma unroll
    for (int i = 0; i < 2; i++) {
#pragma unroll
        for (int rr = 0; rr < 2; rr++) {
            int r = row0 + wm + i * 16 + gid + rr * 8;
            if (r >= M) continue;
            float bm = (BIASMODE == 1) ? bias[r] : 0.f;
#pragma unroll
            for (int j = 0; j < 8; j++) {
                int cc = col0 + wn + j * 8 + 2 * tig;
                float x0 = acc[i][j][2 * rr + 0];
                float x1 = acc[i][j][2 * rr + 1];
                if (BIASMODE == 1) { x0 += bm; x1 += bm; }
                if (BIASMODE == 2) { x0 += bias[cc]; x1 += bias[cc + 1]; }
                if (ACT_SILU) { x0 = siluf(x0); x1 = siluf(x1); }
                if (OUTBF) {
                    bf16* Cz = (bf16*)Cv + (long long)blockIdx.z * strideC;
                    *(__nv_bfloat162*)(Cz + (long long)r * N + cc) = __floats2bfloat162_rn(x0, x1);
                } else {
                    float* Cz = (float*)Cv + (long long)blockIdx.z * strideC;
                    *(float2*)(Cz + (long long)r * N + cc) = make_float2(x0, x1);
                }
            }
        }
    }
}

// ---------------- weight / activation conversion ----------------
__global__ void convw_k(const float* __restrict__ src, bf16* __restrict__ dst, long long n)
{
    long long i = (long long)blockIdx.x * blockDim.x + threadIdx.x;
    long long stride = (long long)gridDim.x * blockDim.x;
    for (; i < n; i += stride) dst[i] = __float2bfloat16(src[i]);
}
__global__ void convsilu_k(const float* __restrict__ src, bf16* __restrict__ dst, long long n)
{
    long long i = (long long)blockIdx.x * blockDim.x + threadIdx.x;
    long long stride = (long long)gridDim.x * blockDim.x;
    for (; i < n; i += stride) dst[i] = __float2bfloat16(siluf(src[i]));
}

// ---------------- LayerNorm reduction ----------------
__global__ void ln_partial_k(const float* __restrict__ x,
                             float* __restrict__ psum, float* __restrict__ psumsq)
{
    int b = blockIdx.y;
    const float* xb = x + (long long)b * SN;
    const int chunk = SN / LNB;
    int base = blockIdx.x * chunk;
    float s = 0.f, sq = 0.f;
    for (int i = base + threadIdx.x; i < base + chunk; i += 256) {
        float v = xb[i]; s += v; sq += v * v;
    }
    __shared__ float sh1[256], sh2[256];
    sh1[threadIdx.x] = s; sh2[threadIdx.x] = sq;
    __syncthreads();
    for (int o = 128; o > 0; o >>= 1) {
        if (threadIdx.x < o) {
            sh1[threadIdx.x] += sh1[threadIdx.x + o];
            sh2[threadIdx.x] += sh2[threadIdx.x + o];
        }
        __syncthreads();
    }
    if (threadIdx.x == 0) {
        psum[b * LNB + blockIdx.x] = sh1[0];
        psumsq[b * LNB + blockIdx.x] = sh2[0];
    }
}

__global__ void ln_final_k(const float* __restrict__ psum, const float* __restrict__ psumsq,
                           float* __restrict__ stats)
{
    int b = blockIdx.x;
    float s = 0.f, sq = 0.f;
    for (int i = threadIdx.x; i < LNB; i += 256) { s += psum[b * LNB + i]; sq += psumsq[b * LNB + i]; }
    __shared__ float sh1[256], sh2[256];
    sh1[threadIdx.x] = s; sh2[threadIdx.x] = sq;
    __syncthreads();
    for (int o = 128; o > 0; o >>= 1) {
        if (threadIdx.x < o) {
            sh1[threadIdx.x] += sh1[threadIdx.x + o];
            sh2[threadIdx.x] += sh2[threadIdx.x + o];
        }
        __syncthreads();
    }
    if (threadIdx.x == 0) {
        float mu = sh1[0] / (float)SN;
        float var = sh2[0] / (float)SN - mu * mu;
        stats[b * 2 + 0] = mu;
        stats[b * 2 + 1] = rsqrtf(var + 1e-6f);
    }
}

// ---------------- token init ----------------
__global__ void tokinit_k(const float* __restrict__ gt, const float* __restrict__ tt,
                          bf16* __restrict__ tok)
{
    int gid = blockIdx.x * blockDim.x + threadIdx.x;
    if (gid >= BN * DD) return;
    int b = gid / DD, j = gid % DD;
    tok[((long long)b * SSEQ + 0) * DD + j] = __float2bfloat16(gt[b * DD + j]);
    tok[((long long)b * SSEQ + 1) * DD + j] = __float2bfloat16(tt[b * DD + j]);
}

// ---------------- MSA modulate + segment -> bf16 tokens ----------------
__global__ void msa_seg_k(const float* __restrict__ x, const float* __restrict__ ss,
                          const float* __restrict__ stats, bf16* __restrict__ tok)
{
    long long gid = (long long)blockIdx.x * blockDim.x + threadIdx.x;
    if (gid >= (long long)BN * STOK * DD) return;
    int j = (int)(gid % DD);
    int t = (int)((gid / DD) % STOK);
    int b = (int)(gid / ((long long)STOK * DD));
    int c = j >> 2, p1 = (j >> 1) & 1, p2 = j & 1;
    int n1 = t >> 5, n2 = t & 31;
    int hw = ((2 * n1 + p1) << 6) + 2 * n2 + p2;
    float mu = stats[b * 2], rsig = stats[b * 2 + 1];
    float xv = x[((long long)b * CCH + c) * HWSZ + hw];
    float sc = ss[((long long)b * SIXC + 288 + c) * HWSZ + hw];
    float sh = ss[((long long)b * SIXC + c) * HWSZ + hw];
    tok[((long long)b * SSEQ + 2 + t) * DD + j] =
        __float2bfloat16((xv - mu) * rsig * (1.f + sc) + sh);
}

// ---------------- linear attention ----------------
__global__ void attn_k(const float* __restrict__ qkv, bf16* __restrict__ attn)
{
    int h = blockIdx.x, b = blockIdx.y;
    int tid = threadIdx.x;
    __shared__ float vk[33 * 32];
    __shared__ float ks[8][32];
    __shared__ float vs[8][33];
    float acc[5] = {0.f, 0.f, 0.f, 0.f, 0.f};
    const float* qkvb = qkv + (long long)b * SSEQ * (3 * DD);

    for (int s0 = 0; s0 < SSEQ; s0 += 8) {
        {
            int si = tid >> 5, d = tid & 31;
            int s = s0 + si;
            ks[si][d] = (s < SSEQ) ? fmaxf(qkvb[(long long)s * (3 * DD) + DD + h * 32 + d], 0.f) : 0.f;
        }
        for (int idx = tid; idx < 8 * 33; idx += 256) {
            int si = idx / 33, e = idx % 33;
            int s = s0 + si;
            float vv = 0.f;
            if (s < SSEQ) vv = (e < 32) ? qkvb[(long long)s * (3 * DD) + 2 * DD + h * 32 + e] : 1.f;
            vs[si][e] = vv;
        }
        __syncthreads();
#pragma unroll
        for (int si = 0; si < 8; si++) {
#pragma unroll
            for (int r = 0; r < 5; r++) {
                int f = tid + (r << 8);
                if (f < 1056) acc[r] += vs[si][f >> 5] * ks[si][f & 31];
            }
        }
        __syncthreads();
    }
#pragma unroll
    for (int r = 0; r < 5; r++) {
        int f = tid + (r << 8);
        if (f < 1056) vk[f] = acc[r];
    }
    __syncthreads();

    for (int s = tid; s < SSEQ; s += 256) {
        float q[32];
        const float* qp = qkvb + (long long)s * (3 * DD) + h * 32;
#pragma unroll
        for (int d4 = 0; d4 < 32; d4 += 4) {
            float4 qv = *(const float4*)(qp + d4);
            q[d4 + 0] = fmaxf(qv.x, 0.f); q[d4 + 1] = fmaxf(qv.y, 0.f);
            q[d4 + 2] = fmaxf(qv.z, 0.f); q[d4 + 3] = fmaxf(qv.w, 0.f);
        }
        float den = 0.f;
#pragma unroll
        for (int d = 0; d < 32; d++) den += vk[32 * 32 + d] * q[d];
        float inv = 1.0f / (den + 1e-8f);
        if (s >= 2) {
            bf16* op = attn + ((long long)(b * STOK + s - 2)) * DD + h * 32;
            for (int e = 0; e < 32; e++) {
                float num = 0.f;
#pragma unroll
                for (int d = 0; d < 32; d++) num += vk[e * 32 + d] * q[d];
                op[e] = __float2bfloat16(num * inv);
            }
        }
    }
}

// ---------------- comb(a)*g_msa + residual -> x1 ----------------
__global__ void comb1_k(const float* __restrict__ x, const float* __restrict__ a,
                        const float* __restrict__ ss, float* __restrict__ x1)
{
    long long gid = (long long)blockIdx.x * blockDim.x + threadIdx.x;
    if (gid >= (long long)BN * SN) return;
    int hw = (int)(gid % HWSZ);
    int c = (int)((gid / HWSZ) % CCH);
    int b = (int)(gid / SN);
    int hh = hw >> 6, ww = hw & 63;
    int t = ((hh >> 1) << 5) + (ww >> 1);
    int j = (c << 2) + ((hh & 1) << 1) + (ww & 1);
    float g = ss[((long long)b * SIXC + 576 + c) * HWSZ + hw];
    x1[gid] = x[gid] + a[((long long)(b * STOK + t)) * DD + j] * g;
}

// ---------------- MLP modulate + segment (transposed) -> bf16 ----------------
__global__ void mlp_segT_k(const float* __restrict__ x1, const float* __restrict__ ss,
                           const float* __restrict__ stats, bf16* __restrict__ t2T)
{
    long long gid = (long long)blockIdx.x * blockDim.x + threadIdx.x;
    if (gid >= (long long)BN * DD * STOK) return;
    int n = (int)(gid % STOK);
    int j = (int)((gid / STOK) % DD);
    int b = (int)(gid / ((long long)DD * STOK));
    int c = j >> 2, p1 = (j >> 1) & 1, p2 = j & 1;
    int n1 = n >> 5, n2 = n & 31;
    int hw = ((2 * n1 + p1) << 6) + 2 * n2 + p2;
    float mu = stats[b * 2], rsig = stats[b * 2 + 1];
    float xv = x1[((long long)b * CCH + c) * HWSZ + hw];
    float sc = ss[((long long)b * SIXC + 1152 + c) * HWSZ + hw];
    float sh = ss[((long long)b * SIXC + 864 + c) * HWSZ + hw];
    t2T[gid] = __float2bfloat16((xv - mu) * rsig * (1.f + sc) + sh);
}

// ---------------- depthwise 3x3 + GLU (bf16 in/out) ----------------
__global__ void dwglu_k(const bf16* __restrict__ hexp, const float* __restrict__ dw_w,
                        const float* __restrict__ dw_b, bf16* __restrict__ hglu)
{
    long long gid = (long long)blockIdx.x * blockDim.x + threadIdx.x;
    if (gid >= (long long)BN * HFF * STOK) return;
    int n = (int)(gid % STOK);
    int ch = (int)((gid / STOK) % HFF);
    int b = (int)(gid / ((long long)HFF * STOK));
    int y = n >> 5, xx = n & 31;
    const bf16* pa = hexp + ((long long)b * HF2 + ch) * STOK;
    const bf16* pg = hexp + ((long long)b * HF2 + ch + HFF) * STOK;
    const float* wa = dw_w + ch * 9;
    const float* wg = dw_w + (ch + HFF) * 9;
    float va = dw_b[ch], vg = dw_b[ch + HFF];
#pragma unroll
    for (int ky = -1; ky <= 1; ky++) {
        int yy = y + ky;
        if ((unsigned)yy >= 32u) continue;
#pragma unroll
        for (int kx = -1; kx <= 1; kx++) {
            int xc = xx + kx;
            if ((unsigned)xc >= 32u) continue;
            int nn = (yy << 5) + xc;
            int wi = (ky + 1) * 3 + (kx + 1);
            va += wa[wi] * __bfloat162float(pa[nn]);
            vg += wg[wi] * __bfloat162float(pg[nn]);
        }
    }
    hglu[gid] = __float2bfloat16(va * siluf(vg));
}

// ---------------- comb(m)*g_mlp + residual -> out ----------------
__global__ void comb2_k(const float* __restrict__ x1, const float* __restrict__ mT,
                        const float* __restrict__ ss, float* __restrict__ out)
{
    long long gid = (long long)blockIdx.x * blockDim.x + threadIdx.x;
    if (gid >= (long long)BN * SN) return;
    int hw = (int)(gid % HWSZ);
    int c = (int)((gid / HWSZ) % CCH);
    int b = (int)(gid / SN);
    int hh = hw >> 6, ww = hw & 63;
    int t = ((hh >> 1) << 5) + (ww >> 1);
    int j = (c << 2) + ((hh & 1) << 1) + (ww & 1);
    float g = ss[((long long)b * SIXC + 1440 + c) * HWSZ + hw];
    out[gid] = x1[gid] + mT[((long long)b * DD + j) * STOK + t] * g;
}

// ---------------- launch ----------------
extern "C" void kernel_launch(void* const* d_in, const int* in_sizes, int n_in,
                              void* d_out, int out_size)
{
    const float* x      = (const float*)d_in[0];
    const float* cond   = (const float*)d_in[1];
    const float* gtok   = (const float*)d_in[2];
    const float* ttok   = (const float*)d_in[3];
    const float* ss_w   = (const float*)d_in[4];
    const float* ss_b   = (const float*)d_in[5];
    const float* qkv_w  = (const float*)d_in[6];
    const float* proj_w = (const float*)d_in[7];
    const float* proj_b = (const float*)d_in[8];
    const float* inv_w  = (const float*)d_in[9];
    const float* inv_b  = (const float*)d_in[10];
    const float* dw_w   = (const float*)d_in[11];
    const float* dw_b   = (const float*)d_in[12];
    const float* pw_w   = (const float*)d_in[13];
    float* out = (float*)d_out;

    float *p_ss, *p_qkv, *p_aproj, *p_x1, *p_mT, *p_psum, *p_psumsq, *p_stats;
    bf16 *p_condb, *p_tok, *p_attn, *p_t2T, *p_hexp, *p_hglu;
    bf16 *p_ssw, *p_qkvw, *p_projw, *p_invw, *p_pww;
    cudaGetSymbolAddress((void**)&p_ss, g_ss);
    cudaGetSymbolAddress((void**)&p_condb, g_condb);
    cudaGetSymbolAddress((void**)&p_tok, g_tok);
    cudaGetSymbolAddress((void**)&p_qkv, g_qkv);
    cudaGetSymbolAddress((void**)&p_attn, g_attn);
    cudaGetSymbolAddress((void**)&p_aproj, g_aproj);
    cudaGetSymbolAddress((void**)&p_x1, g_x1);
    cudaGetSymbolAddress((void**)&p_t2T, g_t2T);
    cudaGetSymbolAddress((void**)&p_hexp, g_hexp);
    cudaGetSymbolAddress((void**)&p_hglu, g_hglu);
    cudaGetSymbolAddress((void**)&p_mT, g_mT);
    cudaGetSymbolAddress((void**)&p_psum, g_psum);
    cudaGetSymbolAddress((void**)&p_psumsq, g_psumsq);
    cudaGetSymbolAddress((void**)&p_stats, g_stats);
    cudaGetSymbolAddress((void**)&p_ssw, g_ssw);
    cudaGetSymbolAddress((void**)&p_qkvw, g_qkvw);
    cudaGetSymbolAddress((void**)&p_projw, g_projw);
    cudaGetSymbolAddress((void**)&p_invw, g_invw);
    cudaGetSymbolAddress((void**)&p_pww, g_pww);

    // 0) weight + cond conversions
    convw_k<<<512, 256>>>(ss_w, p_ssw, (long long)SIXC * SIXC);
    convw_k<<<512, 256>>>(qkv_w, p_qkvw, (long long)3 * DD * DD);
    convw_k<<<512, 256>>>(proj_w, p_projw, (long long)DD * DD);
    convw_k<<<512, 256>>>(inv_w, p_invw, (long long)HF2 * DD);
    convw_k<<<512, 256>>>(pw_w, p_pww, (long long)DD * HFF);
    convsilu_k<<<1024, 256>>>(cond, p_condb, (long long)BN * SIXC * HWSZ);

    // 1) scale_shift: ss[b] = ss_w @ silu(cond[b]) + ss_b  (fp32 out)
    gemm_bf16<false, 1, false, false><<<dim3(HWSZ / 128, (SIXC + 127) / 128, BN), 256>>>(
        p_ssw, p_condb, p_ss, ss_b, SIXC, HWSZ, SIXC,
        (long long)SIXC * HWSZ, (long long)SIXC * HWSZ);

    // 2) LayerNorm(x)
    ln_partial_k<<<dim3(LNB, BN), 256>>>(x, p_psum, p_psumsq);
    ln_final_k<<<BN, 256>>>(p_psum, p_psumsq, p_stats);

    // 3) tokens (bf16)
    tokinit_k<<<(BN * DD + 255) / 256, 256>>>(gtok, ttok, p_tok);
    msa_seg_k<<<(int)(((long long)BN * STOK * DD + 255) / 256), 256>>>(x, p_ss, p_stats, p_tok);

    // 4) qkv = tok @ qkv_w^T  (fp32 out)
    gemm_bf16<true, 0, false, false><<<dim3((3 * DD) / 128, (BN * SSEQ + 127) / 128, 1), 256>>>(
        p_tok, p_qkvw, p_qkv, nullptr, BN * SSEQ, 3 * DD, DD, 0, 0);

    // 5) linear attention (bf16 out)
    attn_k<<<dim3(NHEADS, BN), 256>>>(p_qkv, p_attn);

    // 6) proj = attn @ proj_w^T + proj_b  (fp32 out)
    gemm_bf16<true, 2, false, false><<<dim3(DD / 128, (BN * STOK) / 128, 1), 256>>>(
        p_attn, p_projw, p_aproj, proj_b, BN * STOK, DD, DD, 0, 0);

    // 7) x1 = x + comb(a)*g_msa
    comb1_k<<<(int)(((long long)BN * SN + 255) / 256), 256>>>(x, p_aproj, p_ss, p_x1);

    // 8) LayerNorm(x1)
    ln_partial_k<<<dim3(LNB, BN), 256>>>(p_x1, p_psum, p_psumsq);
    ln_final_k<<<BN, 256>>>(p_psum, p_psumsq, p_stats);

    // 9) MLP modulate+segment (bf16, transposed)
    mlp_segT_k<<<(int)(((long long)BN * DD * STOK + 255) / 256), 256>>>(p_x1, p_ss, p_stats, p_t2T);

    // 10) expand: hexp[b] = silu(inv_w @ t2T[b] + inv_b)  (bf16 out)
    gemm_bf16<false, 1, true, true><<<dim3(STOK / 128, HF2 / 128, BN), 256>>>(
        p_invw, p_t2T, p_hexp, inv_b, HF2, STOK, DD,
        (long long)DD * STOK, (long long)HF2 * STOK);

    // 11) depthwise 3x3 + GLU (bf16 -> bf16)
    dwglu_k<<<(int)(((long long)BN * HFF * STOK + 255) / 256), 256>>>(p_hexp, dw_w, dw_b, p_hglu);

    // 12) project: mT[b] = pw_w @ hglu[b]  (fp32 out)
    gemm_bf16<false, 0, false, false><<<dim3(STOK / 128, DD / 128, BN), 256>>>(
        p_pww, p_hglu, p_mT, nullptr, DD, STOK, HFF,
        (long long)HFF * STOK, (long long)DD * STOK);

    // 13) out = x1 + comb(m)*g_mlp
    comb2_k<<<(int)(((long long)BN * SN + 255) / 256), 256>>>(p_x1, p_mT, p_ss, out);
}